// round 2
// baseline (speedup 1.0000x reference)
#include <cuda_runtime.h>
#include <cstdint>
#include <cstddef>

#define N_NODES 100000
#define F_IN 128
#define HID 256

// ---------------- scratch (device globals; no allocation allowed) ----------------
__device__ int g_idx64;                 // 1 if index arrays are int64, 0 if int32
__device__ float g_cnt[N_NODES];
__device__ float g_rcnt[N_NODES];
__device__ float g_agg1[(size_t)N_NODES * F_IN];
__device__ float g_h1[(size_t)N_NODES * HID];
__device__ float g_agg2[(size_t)N_NODES * HID];
__device__ float g_h2[(size_t)N_NODES * HID];

// ---------------- index dtype sniff ----------------
// If indices are int64 (values < 2^31), the high 32-bit word of each entry is 0.
// If int32, those word positions hold random node ids; 64 consecutive zeros is
// impossible in practice ( (1e-5)^64 ).
__global__ void sniff_kernel(const int* __restrict__ e) {
    if (threadIdx.x == 0 && blockIdx.x == 0) {
        int allz = 1;
        for (int i = 0; i < 64; i++)
            if (e[2 * i + 1] != 0) { allz = 0; break; }
        g_idx64 = allz;
    }
}

__device__ __forceinline__ int load_idx(const void* __restrict__ p, size_t i, int is64) {
    if (is64) return (int)((const long long*)p)[i];
    return ((const int*)p)[i];
}

// ---------------- zero all accumulators ----------------
__global__ void zero_all_kernel() {
    size_t i = (size_t)blockIdx.x * blockDim.x + threadIdx.x;
    size_t stride = (size_t)gridDim.x * blockDim.x;
    const size_t n1 = (size_t)N_NODES * F_IN / 4;
    const size_t n2 = (size_t)N_NODES * HID / 4;
    const size_t nc = N_NODES / 4;
    float4 z = make_float4(0.f, 0.f, 0.f, 0.f);
    for (size_t k = i; k < n1; k += stride) reinterpret_cast<float4*>(g_agg1)[k] = z;
    for (size_t k = i; k < n2; k += stride) reinterpret_cast<float4*>(g_agg2)[k] = z;
    for (size_t k = i; k < nc; k += stride) reinterpret_cast<float4*>(g_cnt)[k] = z;
}

// ---------------- layer-1 scatter: agg1[dst] += x[src], cnt[dst] += 1 ----------------
__global__ void scatter1_kernel(const float* __restrict__ x,
                                const void* __restrict__ edge, int E) {
    int w = (int)(((size_t)blockIdx.x * blockDim.x + threadIdx.x) >> 5);
    if (w >= E) return;
    int is64 = g_idx64;
    int lane = threadIdx.x & 31;
    int s = load_idx(edge, w, is64);
    int d = load_idx(edge, (size_t)E + w, is64);
    float4 v = reinterpret_cast<const float4*>(x + (size_t)s * F_IN)[lane];
    float* ag = g_agg1 + (size_t)d * F_IN + lane * 4;
    atomicAdd(ag + 0, v.x);
    atomicAdd(ag + 1, v.y);
    atomicAdd(ag + 2, v.z);
    atomicAdd(ag + 3, v.w);
    if (lane == 0) atomicAdd(g_cnt + d, 1.0f);
}

// ---------------- layer-2 scatter: agg2[dst] += h1[src] (256 feats) ----------------
__global__ void scatter2_kernel(const void* __restrict__ edge, int E) {
    int w = (int)(((size_t)blockIdx.x * blockDim.x + threadIdx.x) >> 5);
    if (w >= E) return;
    int is64 = g_idx64;
    int lane = threadIdx.x & 31;
    int s = load_idx(edge, w, is64);
    int d = load_idx(edge, (size_t)E + w, is64);
    const float4* hp = reinterpret_cast<const float4*>(g_h1 + (size_t)s * HID);
    float4 v0 = hp[lane];
    float4 v1 = hp[lane + 32];
    float* ag = g_agg2 + (size_t)d * HID;
    float* a0 = ag + lane * 4;
    float* a1 = ag + 128 + lane * 4;
    atomicAdd(a0 + 0, v0.x);
    atomicAdd(a0 + 1, v0.y);
    atomicAdd(a0 + 2, v0.z);
    atomicAdd(a0 + 3, v0.w);
    atomicAdd(a1 + 0, v1.x);
    atomicAdd(a1 + 1, v1.y);
    atomicAdd(a1 + 2, v1.z);
    atomicAdd(a1 + 3, v1.w);
}

// ---------------- reciprocal counts ----------------
__global__ void rcnt_kernel() {
    int i = blockIdx.x * blockDim.x + threadIdx.x;
    if (i < N_NODES) g_rcnt[i] = 1.0f / fmaxf(g_cnt[i], 1.0f);
}

// ---------------- scale agg rows by rcnt (mean) ----------------
__global__ void scale_rows_kernel(float* __restrict__ agg, int logF4, size_t n4) {
    size_t i = (size_t)blockIdx.x * blockDim.x + threadIdx.x;
    if (i >= n4) return;
    size_t row = i >> logF4;
    float r = g_rcnt[row];
    float4 v = reinterpret_cast<float4*>(agg)[i];
    v.x *= r; v.y *= r; v.z *= r; v.w *= r;
    reinterpret_cast<float4*>(agg)[i] = v;
}

// ---------------- fused dual-input SGEMM + bias + relu ----------------
// C[M,256] = relu( A0[M,K0] @ W0[K0,256] + A1[M,K1] @ W1[K1,256] + bias )
// K0, K1 multiples of 16 so each k-tile lives wholly in one matrix.
__global__ __launch_bounds__(256) void gemm_dual_relu_kernel(
    const float* __restrict__ A0, int K0,
    const float* __restrict__ A1, int K1,
    const float* __restrict__ W0, const float* __restrict__ W1w,
    const float* __restrict__ bias, float* __restrict__ C, int M) {
    const int N = 256;
    __shared__ float As[16][136];
    __shared__ float Bs[16][128];
    int tid = threadIdx.x;
    int bm = blockIdx.x * 128;
    int bn = blockIdx.y * 128;
    int tx = tid & 15;
    int ty = tid >> 4;
    float acc[8][8];
#pragma unroll
    for (int i = 0; i < 8; i++)
#pragma unroll
        for (int j = 0; j < 8; j++) acc[i][j] = 0.f;

    int arow = tid >> 1;        // 0..127
    int akk = (tid & 1) * 8;    // 0 or 8
    int brow = tid >> 4;        // 0..15
    int bnn = (tid & 15) * 8;   // 0..120
    int K = K0 + K1;

    for (int kt = 0; kt < K; kt += 16) {
        const float* Ap;
        const float* Wp;
        int lda, kloc;
        if (kt < K0) { Ap = A0; Wp = W0; lda = K0; kloc = kt; }
        else         { Ap = A1; Wp = W1w; lda = K1; kloc = kt - K0; }

        float4 a0 = make_float4(0.f, 0.f, 0.f, 0.f);
        float4 a1 = a0;
        int grow = bm + arow;
        if (grow < M) {
            const float4* srcp = reinterpret_cast<const float4*>(Ap + (size_t)grow * lda + kloc + akk);
            a0 = srcp[0];
            a1 = srcp[1];
        }
        As[akk + 0][arow] = a0.x; As[akk + 1][arow] = a0.y;
        As[akk + 2][arow] = a0.z; As[akk + 3][arow] = a0.w;
        As[akk + 4][arow] = a1.x; As[akk + 5][arow] = a1.y;
        As[akk + 6][arow] = a1.z; As[akk + 7][arow] = a1.w;

        const float4* wsrc = reinterpret_cast<const float4*>(Wp + (size_t)(kloc + brow) * N + bn + bnn);
        float4 b0 = wsrc[0];
        float4 b1 = wsrc[1];
        *reinterpret_cast<float4*>(&Bs[brow][bnn]) = b0;
        *reinterpret_cast<float4*>(&Bs[brow][bnn + 4]) = b1;
        __syncthreads();

#pragma unroll
        for (int k = 0; k < 16; k++) {
            float ar[8], br[8];
#pragma unroll
            for (int i = 0; i < 8; i++) ar[i] = As[k][ty * 8 + i];
#pragma unroll
            for (int j = 0; j < 8; j++) br[j] = Bs[k][tx * 8 + j];
#pragma unroll
            for (int i = 0; i < 8; i++)
#pragma unroll
                for (int j = 0; j < 8; j++) acc[i][j] += ar[i] * br[j];
        }
        __syncthreads();
    }

#pragma unroll
    for (int i = 0; i < 8; i++) {
        int r = bm + ty * 8 + i;
        if (r < M) {
#pragma unroll
            for (int j = 0; j < 8; j++) {
                int c = bn + tx * 8 + j;
                float v = acc[i][j] + bias[c];
                C[(size_t)r * N + c] = v > 0.f ? v : 0.f;
            }
        }
    }
}

// ---------------- MLP head: warp per batch row ----------------
__global__ __launch_bounds__(256) void mlp_kernel(
    const float* __restrict__ x_tab, const void* __restrict__ idx,
    const float* __restrict__ W1, const float* __restrict__ b1,
    const float* __restrict__ W2, const float* __restrict__ b2,
    const float* __restrict__ W3, const float* __restrict__ b3,
    float* __restrict__ out, int B) {
    __shared__ float zs[8][280];
    __shared__ float z1s[8][64];
    int w = threadIdx.x >> 5;
    int lane = threadIdx.x & 31;
    int row = blockIdx.x * 8 + w;
    if (row >= B) return;
    int node = load_idx(idx, row, g_idx64);
    const float4* h = reinterpret_cast<const float4*>(g_h2 + (size_t)node * HID);
    float4 v = h[lane];
    *reinterpret_cast<float4*>(&zs[w][lane * 4]) = v;
    v = h[lane + 32];
    *reinterpret_cast<float4*>(&zs[w][128 + lane * 4]) = v;
    if (lane < 16) zs[w][256 + lane] = x_tab[row * 16 + lane];
    __syncwarp();

    float a0 = b1[lane];
    float a1 = b1[lane + 32];
#pragma unroll 4
    for (int k = 0; k < 272; k++) {
        float zk = zs[w][k];
        a0 += zk * W1[k * 64 + lane];
        a1 += zk * W1[k * 64 + lane + 32];
    }
    z1s[w][lane] = fmaxf(a0, 0.f);
    z1s[w][lane + 32] = fmaxf(a1, 0.f);
    __syncwarp();

    float a = b2[lane];
#pragma unroll
    for (int k = 0; k < 64; k++) a += z1s[w][k] * W2[k * 32 + lane];
    float z2 = fmaxf(a, 0.f);

    float p = z2 * W3[lane];
#pragma unroll
    for (int off = 16; off; off >>= 1) p += __shfl_down_sync(0xffffffffu, p, off);
    if (lane == 0) out[row] = p + b3[0];
}

// ---------------- launch ----------------
extern "C" void kernel_launch(void* const* d_in, const int* in_sizes, int n_in,
                              void* d_out, int out_size) {
    const float* x     = (const float*)d_in[0];
    const void* edge   = d_in[1];
    const void* idxb   = d_in[2];
    const float* x_tab = (const float*)d_in[3];
    const float* Wl1 = (const float*)d_in[4];
    const float* bl1 = (const float*)d_in[5];
    const float* Wr1 = (const float*)d_in[6];
    const float* Wl2 = (const float*)d_in[7];
    const float* bl2 = (const float*)d_in[8];
    const float* Wr2 = (const float*)d_in[9];
    const float* W1  = (const float*)d_in[10];
    const float* b1  = (const float*)d_in[11];
    const float* W2  = (const float*)d_in[12];
    const float* b2  = (const float*)d_in[13];
    const float* W3  = (const float*)d_in[14];
    const float* b3  = (const float*)d_in[15];
    float* out = (float*)d_out;

    int E = in_sizes[1] / 2;   // logical edge count (element count matches dtype either way)
    int B = in_sizes[2];

    float *p_agg1, *p_agg2, *p_h1, *p_h2;
    cudaGetSymbolAddress((void**)&p_agg1, g_agg1);
    cudaGetSymbolAddress((void**)&p_agg2, g_agg2);
    cudaGetSymbolAddress((void**)&p_h1, g_h1);
    cudaGetSymbolAddress((void**)&p_h2, g_h2);

    // 0. detect index dtype (int32 vs int64)
    sniff_kernel<<<1, 32>>>((const int*)edge);

    // 1. zero accumulators
    zero_all_kernel<<<4096, 256>>>();

    // 2. layer-1 scatter (+ degree count)
    scatter1_kernel<<<(E + 7) / 8, 256>>>(x, edge, E);

    // 3. reciprocal counts
    rcnt_kernel<<<(N_NODES + 255) / 256, 256>>>();

    // 4. mean for layer 1
    {
        size_t n4 = (size_t)N_NODES * F_IN / 4;
        scale_rows_kernel<<<(int)((n4 + 255) / 256), 256>>>(p_agg1, 5, n4);
    }

    // 5. h1 = relu(mean1 @ Wl1 + x @ Wr1 + bl1)
    {
        dim3 grid((N_NODES + 127) / 128, 2);
        gemm_dual_relu_kernel<<<grid, 256>>>(p_agg1, F_IN, x, F_IN, Wl1, Wr1, bl1, p_h1, N_NODES);
    }

    // 6. layer-2 scatter
    scatter2_kernel<<<(E + 7) / 8, 256>>>(edge, E);

    // 7. mean for layer 2
    {
        size_t n4 = (size_t)N_NODES * HID / 4;
        scale_rows_kernel<<<(int)((n4 + 255) / 256), 256>>>(p_agg2, 6, n4);
    }

    // 8. h2 = relu(mean2 @ Wl2 + h1 @ Wr2 + bl2)
    {
        dim3 grid((N_NODES + 127) / 128, 2);
        gemm_dual_relu_kernel<<<grid, 256>>>(p_agg2, HID, p_h1, HID, Wl2, Wr2, bl2, p_h2, N_NODES);
    }

    // 9. MLP head
    mlp_kernel<<<(B + 7) / 8, 256>>>(x_tab, idxb, W1, b1, W2, b2, W3, b3, out, B);
}

// round 3
// speedup vs baseline: 1.8697x; 1.8697x over previous
#include <cuda_runtime.h>
#include <cstdint>
#include <cstddef>

#define N_NODES 100000
#define F_IN 128
#define HID 256
#define E_MAX 1600000

// ---------------- scratch (device globals; no allocation allowed) ----------------
__device__ int g_idx64;                    // 1 if index arrays are int64, 0 if int32
__device__ int g_deg[N_NODES];             // degree (atomic count)
__device__ int g_rowstart[N_NODES + 1];    // CSR row offsets
__device__ int g_wptr[N_NODES];            // fill cursors (init = rowstart)
__device__ int g_csr[E_MAX];               // src node per CSR slot
__device__ float g_agg1[(size_t)N_NODES * F_IN];
__device__ float g_h1[(size_t)N_NODES * HID];
__device__ float g_agg2[(size_t)N_NODES * HID];
__device__ float g_h2[(size_t)N_NODES * HID];

// ---------------- index dtype sniff ----------------
// int64 values < 2^31 have zero high words; 64 consecutive zero high words is
// impossible for an int32 stream of random node ids.
__global__ void sniff_kernel(const int* __restrict__ e) {
    if (threadIdx.x == 0 && blockIdx.x == 0) {
        int allz = 1;
        for (int i = 0; i < 64; i++)
            if (e[2 * i + 1] != 0) { allz = 0; break; }
        g_idx64 = allz;
    }
}

__device__ __forceinline__ int load_idx(const void* __restrict__ p, size_t i, int is64) {
    if (is64) return (int)((const long long*)p)[i];
    return ((const int*)p)[i];
}

// ---------------- zero degree counters ----------------
__global__ void zero_deg_kernel() {
    int i = blockIdx.x * blockDim.x + threadIdx.x;
    if (i < N_NODES) g_deg[i] = 0;
}

// ---------------- degree count: deg[dst]++ ----------------
__global__ void degree_kernel(const void* __restrict__ edge, int E) {
    int e = blockIdx.x * blockDim.x + threadIdx.x;
    if (e >= E) return;
    int d = load_idx(edge, (size_t)E + e, g_idx64);
    atomicAdd(&g_deg[d], 1);
}

// ---------------- single-block exclusive scan over degrees ----------------
__global__ __launch_bounds__(1024) void scan_kernel() {
    __shared__ int wsum[32];
    __shared__ int s_off;
    int tid = threadIdx.x;
    int lane = tid & 31;
    int wid = tid >> 5;
    if (tid == 0) s_off = 0;
    __syncthreads();
    for (int base = 0; base < N_NODES; base += 1024) {
        int i = base + tid;
        int v = (i < N_NODES) ? g_deg[i] : 0;
        // inclusive warp scan
        int s = v;
#pragma unroll
        for (int o = 1; o < 32; o <<= 1) {
            int t = __shfl_up_sync(0xffffffffu, s, o);
            if (lane >= o) s += t;
        }
        if (lane == 31) wsum[wid] = s;
        __syncthreads();
        if (wid == 0) {
            int ws = wsum[lane];
            int ss = ws;
#pragma unroll
            for (int o = 1; o < 32; o <<= 1) {
                int t = __shfl_up_sync(0xffffffffu, ss, o);
                if (lane >= o) ss += t;
            }
            wsum[lane] = ss;
        }
        __syncthreads();
        int excl = s - v + (wid ? wsum[wid - 1] : 0) + s_off;
        if (i < N_NODES) {
            g_rowstart[i] = excl;
            g_wptr[i] = excl;
        }
        int total = wsum[31];
        __syncthreads();
        if (tid == 0) s_off += total;
        __syncthreads();
    }
    if (tid == 0) g_rowstart[N_NODES] = s_off;
}

// ---------------- CSR fill: slot per edge ----------------
__global__ void fill_kernel(const void* __restrict__ edge, int E) {
    int e = blockIdx.x * blockDim.x + threadIdx.x;
    if (e >= E) return;
    int is64 = g_idx64;
    int s = load_idx(edge, e, is64);
    int d = load_idx(edge, (size_t)E + e, is64);
    int pos = atomicAdd(&g_wptr[d], 1);
    g_csr[pos] = s;
}

// ---------------- layer-1 aggregate: agg1[n] = mean over neighbors of x[src] ----------------
// one warp per node; 4 floats per lane (row = 128 floats)
__global__ __launch_bounds__(256) void agg1_kernel(const float* __restrict__ x) {
    int n = (int)(((size_t)blockIdx.x * blockDim.x + threadIdx.x) >> 5);
    if (n >= N_NODES) return;
    int lane = threadIdx.x & 31;
    int start = g_rowstart[n];
    int end = g_rowstart[n + 1];
    float4 acc0 = make_float4(0.f, 0.f, 0.f, 0.f);
    float4 acc1 = make_float4(0.f, 0.f, 0.f, 0.f);
    int e = start;
    for (; e + 1 < end; e += 2) {
        int s0 = g_csr[e];
        int s1 = g_csr[e + 1];
        float4 v0 = reinterpret_cast<const float4*>(x + (size_t)s0 * F_IN)[lane];
        float4 v1 = reinterpret_cast<const float4*>(x + (size_t)s1 * F_IN)[lane];
        acc0.x += v0.x; acc0.y += v0.y; acc0.z += v0.z; acc0.w += v0.w;
        acc1.x += v1.x; acc1.y += v1.y; acc1.z += v1.z; acc1.w += v1.w;
    }
    if (e < end) {
        int s0 = g_csr[e];
        float4 v0 = reinterpret_cast<const float4*>(x + (size_t)s0 * F_IN)[lane];
        acc0.x += v0.x; acc0.y += v0.y; acc0.z += v0.z; acc0.w += v0.w;
    }
    float r = 1.0f / fmaxf((float)(end - start), 1.0f);
    float4 o;
    o.x = (acc0.x + acc1.x) * r;
    o.y = (acc0.y + acc1.y) * r;
    o.z = (acc0.z + acc1.z) * r;
    o.w = (acc0.w + acc1.w) * r;
    reinterpret_cast<float4*>(g_agg1 + (size_t)n * F_IN)[lane] = o;
}

// ---------------- layer-2 aggregate: agg2[n] = mean over neighbors of h1[src] ----------------
// one warp per node; 8 floats per lane (row = 256 floats)
__global__ __launch_bounds__(256) void agg2_kernel() {
    int n = (int)(((size_t)blockIdx.x * blockDim.x + threadIdx.x) >> 5);
    if (n >= N_NODES) return;
    int lane = threadIdx.x & 31;
    int start = g_rowstart[n];
    int end = g_rowstart[n + 1];
    float4 a0 = make_float4(0.f, 0.f, 0.f, 0.f);
    float4 a1 = make_float4(0.f, 0.f, 0.f, 0.f);
    for (int e = start; e < end; e++) {
        int s = g_csr[e];
        const float4* hp = reinterpret_cast<const float4*>(g_h1 + (size_t)s * HID);
        float4 v0 = hp[lane];
        float4 v1 = hp[lane + 32];
        a0.x += v0.x; a0.y += v0.y; a0.z += v0.z; a0.w += v0.w;
        a1.x += v1.x; a1.y += v1.y; a1.z += v1.z; a1.w += v1.w;
    }
    float r = 1.0f / fmaxf((float)(end - start), 1.0f);
    a0.x *= r; a0.y *= r; a0.z *= r; a0.w *= r;
    a1.x *= r; a1.y *= r; a1.z *= r; a1.w *= r;
    float4* op = reinterpret_cast<float4*>(g_agg2 + (size_t)n * HID);
    op[lane] = a0;
    op[lane + 32] = a1;
}

// ---------------- fused dual-input SGEMM + bias + relu ----------------
// C[M,256] = relu( A0[M,K0] @ W0[K0,256] + A1[M,K1] @ W1[K1,256] + bias )
__global__ __launch_bounds__(256) void gemm_dual_relu_kernel(
    const float* __restrict__ A0, int K0,
    const float* __restrict__ A1, int K1,
    const float* __restrict__ W0, const float* __restrict__ W1w,
    const float* __restrict__ bias, float* __restrict__ C, int M) {
    const int N = 256;
    __shared__ float As[16][136];
    __shared__ float Bs[16][128];
    int tid = threadIdx.x;
    int bm = blockIdx.x * 128;
    int bn = blockIdx.y * 128;
    int tx = tid & 15;
    int ty = tid >> 4;
    float acc[8][8];
#pragma unroll
    for (int i = 0; i < 8; i++)
#pragma unroll
        for (int j = 0; j < 8; j++) acc[i][j] = 0.f;

    int arow = tid >> 1;
    int akk = (tid & 1) * 8;
    int brow = tid >> 4;
    int bnn = (tid & 15) * 8;
    int K = K0 + K1;

    for (int kt = 0; kt < K; kt += 16) {
        const float* Ap;
        const float* Wp;
        int lda, kloc;
        if (kt < K0) { Ap = A0; Wp = W0; lda = K0; kloc = kt; }
        else         { Ap = A1; Wp = W1w; lda = K1; kloc = kt - K0; }

        float4 a0 = make_float4(0.f, 0.f, 0.f, 0.f);
        float4 a1 = a0;
        int grow = bm + arow;
        if (grow < M) {
            const float4* srcp = reinterpret_cast<const float4*>(Ap + (size_t)grow * lda + kloc + akk);
            a0 = srcp[0];
            a1 = srcp[1];
        }
        As[akk + 0][arow] = a0.x; As[akk + 1][arow] = a0.y;
        As[akk + 2][arow] = a0.z; As[akk + 3][arow] = a0.w;
        As[akk + 4][arow] = a1.x; As[akk + 5][arow] = a1.y;
        As[akk + 6][arow] = a1.z; As[akk + 7][arow] = a1.w;

        const float4* wsrc = reinterpret_cast<const float4*>(Wp + (size_t)(kloc + brow) * N + bn + bnn);
        float4 b0 = wsrc[0];
        float4 b1 = wsrc[1];
        *reinterpret_cast<float4*>(&Bs[brow][bnn]) = b0;
        *reinterpret_cast<float4*>(&Bs[brow][bnn + 4]) = b1;
        __syncthreads();

#pragma unroll
        for (int k = 0; k < 16; k++) {
            float ar[8], br[8];
#pragma unroll
            for (int i = 0; i < 8; i++) ar[i] = As[k][ty * 8 + i];
#pragma unroll
            for (int j = 0; j < 8; j++) br[j] = Bs[k][tx * 8 + j];
#pragma unroll
            for (int i = 0; i < 8; i++)
#pragma unroll
                for (int j = 0; j < 8; j++) acc[i][j] += ar[i] * br[j];
        }
        __syncthreads();
    }

#pragma unroll
    for (int i = 0; i < 8; i++) {
        int r = bm + ty * 8 + i;
        if (r < M) {
#pragma unroll
            for (int j = 0; j < 8; j++) {
                int c = bn + tx * 8 + j;
                float v = acc[i][j] + bias[c];
                C[(size_t)r * N + c] = v > 0.f ? v : 0.f;
            }
        }
    }
}

// ---------------- MLP head: warp per batch row ----------------
__global__ __launch_bounds__(256) void mlp_kernel(
    const float* __restrict__ x_tab, const void* __restrict__ idx,
    const float* __restrict__ W1, const float* __restrict__ b1,
    const float* __restrict__ W2, const float* __restrict__ b2,
    const float* __restrict__ W3, const float* __restrict__ b3,
    float* __restrict__ out, int B) {
    __shared__ float zs[8][280];
    __shared__ float z1s[8][64];
    int w = threadIdx.x >> 5;
    int lane = threadIdx.x & 31;
    int row = blockIdx.x * 8 + w;
    if (row >= B) return;
    int node = load_idx(idx, row, g_idx64);
    const float4* h = reinterpret_cast<const float4*>(g_h2 + (size_t)node * HID);
    float4 v = h[lane];
    *reinterpret_cast<float4*>(&zs[w][lane * 4]) = v;
    v = h[lane + 32];
    *reinterpret_cast<float4*>(&zs[w][128 + lane * 4]) = v;
    if (lane < 16) zs[w][256 + lane] = x_tab[row * 16 + lane];
    __syncwarp();

    float a0 = b1[lane];
    float a1 = b1[lane + 32];
#pragma unroll 4
    for (int k = 0; k < 272; k++) {
        float zk = zs[w][k];
        a0 += zk * W1[k * 64 + lane];
        a1 += zk * W1[k * 64 + lane + 32];
    }
    z1s[w][lane] = fmaxf(a0, 0.f);
    z1s[w][lane + 32] = fmaxf(a1, 0.f);
    __syncwarp();

    float a = b2[lane];
#pragma unroll
    for (int k = 0; k < 64; k++) a += z1s[w][k] * W2[k * 32 + lane];
    float z2 = fmaxf(a, 0.f);

    float p = z2 * W3[lane];
#pragma unroll
    for (int off = 16; off; off >>= 1) p += __shfl_down_sync(0xffffffffu, p, off);
    if (lane == 0) out[row] = p + b3[0];
}

// ---------------- launch ----------------
extern "C" void kernel_launch(void* const* d_in, const int* in_sizes, int n_in,
                              void* d_out, int out_size) {
    const float* x     = (const float*)d_in[0];
    const void* edge   = d_in[1];
    const void* idxb   = d_in[2];
    const float* x_tab = (const float*)d_in[3];
    const float* Wl1 = (const float*)d_in[4];
    const float* bl1 = (const float*)d_in[5];
    const float* Wr1 = (const float*)d_in[6];
    const float* Wl2 = (const float*)d_in[7];
    const float* bl2 = (const float*)d_in[8];
    const float* Wr2 = (const float*)d_in[9];
    const float* W1  = (const float*)d_in[10];
    const float* b1  = (const float*)d_in[11];
    const float* W2  = (const float*)d_in[12];
    const float* b2  = (const float*)d_in[13];
    const float* W3  = (const float*)d_in[14];
    const float* b3  = (const float*)d_in[15];
    float* out = (float*)d_out;

    int E = in_sizes[1] / 2;
    if (E > E_MAX) E = E_MAX;
    int B = in_sizes[2];

    float *p_agg1, *p_agg2, *p_h1, *p_h2;
    cudaGetSymbolAddress((void**)&p_agg1, g_agg1);
    cudaGetSymbolAddress((void**)&p_agg2, g_agg2);
    cudaGetSymbolAddress((void**)&p_h1, g_h1);
    cudaGetSymbolAddress((void**)&p_h2, g_h2);

    // 0. index dtype sniff
    sniff_kernel<<<1, 32>>>((const int*)edge);

    // 1. CSR build
    zero_deg_kernel<<<(N_NODES + 255) / 256, 256>>>();
    degree_kernel<<<(E + 255) / 256, 256>>>(edge, E);
    scan_kernel<<<1, 1024>>>();
    fill_kernel<<<(E + 255) / 256, 256>>>(edge, E);

    // 2. layer-1 mean aggregate (warp per node)
    agg1_kernel<<<(N_NODES * 32 + 255) / 256, 256>>>(x);

    // 3. h1 = relu(mean1 @ Wl1 + x @ Wr1 + bl1)
    {
        dim3 grid((N_NODES + 127) / 128, 2);
        gemm_dual_relu_kernel<<<grid, 256>>>(p_agg1, F_IN, x, F_IN, Wl1, Wr1, bl1, p_h1, N_NODES);
    }

    // 4. layer-2 mean aggregate
    agg2_kernel<<<(N_NODES * 32 + 255) / 256, 256>>>();

    // 5. h2 = relu(mean2 @ Wl2 + h1 @ Wr2 + bl2)
    {
        dim3 grid((N_NODES + 127) / 128, 2);
        gemm_dual_relu_kernel<<<grid, 256>>>(p_agg2, HID, p_h1, HID, Wl2, Wr2, bl2, p_h2, N_NODES);
    }

    // 6. MLP head
    mlp_kernel<<<(B + 7) / 8, 256>>>(x_tab, idxb, W1, b1, W2, b2, W3, b3, out, B);
}

// round 4
// speedup vs baseline: 2.4036x; 1.2855x over previous
#include <cuda_runtime.h>
#include <cuda_bf16.h>
#include <cstdint>
#include <cstddef>

#define N_NODES 100000
#define F_IN 128
#define HID 256
#define E_MAX 1600000
#define NBLK_SCAN ((N_NODES + 255) / 256)

// ---------------- scratch (device globals; no allocation allowed) ----------------
__device__ int g_idx64;
__device__ int g_deg[N_NODES];
__device__ int g_bsum[NBLK_SCAN + 1];
__device__ int g_rowstart[N_NODES + 1];
__device__ int g_wptr[N_NODES];
__device__ int g_csr[E_MAX];
__device__ float g_agg1[(size_t)N_NODES * F_IN];
__device__ float g_h1[(size_t)N_NODES * HID];
__device__ float g_agg2[(size_t)N_NODES * HID];
__device__ float g_h2[(size_t)N_NODES * HID];

// ---------------- index dtype sniff ----------------
__global__ void sniff_kernel(const int* __restrict__ e) {
    if (threadIdx.x == 0 && blockIdx.x == 0) {
        int allz = 1;
        for (int i = 0; i < 64; i++)
            if (e[2 * i + 1] != 0) { allz = 0; break; }
        g_idx64 = allz;
    }
}

__device__ __forceinline__ int load_idx(const void* __restrict__ p, size_t i, int is64) {
    if (is64) return (int)((const long long*)p)[i];
    return ((const int*)p)[i];
}

// ---------------- CSR build ----------------
__global__ void zero_deg_kernel() {
    int i = blockIdx.x * blockDim.x + threadIdx.x;
    if (i < N_NODES) g_deg[i] = 0;
}

__global__ void degree_kernel(const void* __restrict__ edge, int E) {
    int e = blockIdx.x * blockDim.x + threadIdx.x;
    if (e >= E) return;
    int d = load_idx(edge, (size_t)E + e, g_idx64);
    atomicAdd(&g_deg[d], 1);
}

// per-block sums of degrees
__global__ void blocksum_kernel() {
    __shared__ int ws[8];
    int i = blockIdx.x * 256 + threadIdx.x;
    int v = (i < N_NODES) ? g_deg[i] : 0;
    int lane = threadIdx.x & 31, wid = threadIdx.x >> 5;
#pragma unroll
    for (int o = 16; o; o >>= 1) v += __shfl_down_sync(0xffffffffu, v, o);
    if (lane == 0) ws[wid] = v;
    __syncthreads();
    if (threadIdx.x == 0) {
        int s = 0;
#pragma unroll
        for (int k = 0; k < 8; k++) s += ws[k];
        g_bsum[blockIdx.x] = s;
    }
}

// single-block exclusive scan of block sums (NBLK_SCAN <= 512)
__global__ __launch_bounds__(512) void scan_bsum_kernel(int E) {
    __shared__ int wsum[16];
    int tid = threadIdx.x, lane = tid & 31, wid = tid >> 5;
    int v = (tid < NBLK_SCAN) ? g_bsum[tid] : 0;
    int s = v;
#pragma unroll
    for (int o = 1; o < 32; o <<= 1) {
        int t = __shfl_up_sync(0xffffffffu, s, o);
        if (lane >= o) s += t;
    }
    if (lane == 31) wsum[wid] = s;
    __syncthreads();
    if (wid == 0 && lane < 16) {
        int ws = wsum[lane];
        int ss = ws;
#pragma unroll
        for (int o = 1; o < 16; o <<= 1) {
            int t = __shfl_up_sync(0xffffu, ss, o);
            if (lane >= o) ss += t;
        }
        wsum[lane] = ss;
    }
    __syncthreads();
    int excl = s - v + (wid ? wsum[wid - 1] : 0);
    if (tid < NBLK_SCAN) g_bsum[tid] = excl;
    if (tid == 0) g_rowstart[N_NODES] = E;
}

// per-block scan + add block offset -> rowstart, wptr
__global__ void distribute_kernel() {
    __shared__ int wsum[8];
    int tid = threadIdx.x, lane = tid & 31, wid = tid >> 5;
    int i = blockIdx.x * 256 + tid;
    int v = (i < N_NODES) ? g_deg[i] : 0;
    int s = v;
#pragma unroll
    for (int o = 1; o < 32; o <<= 1) {
        int t = __shfl_up_sync(0xffffffffu, s, o);
        if (lane >= o) s += t;
    }
    if (lane == 31) wsum[wid] = s;
    __syncthreads();
    if (wid == 0 && lane < 8) {
        int ws = wsum[lane];
        int ss = ws;
#pragma unroll
        for (int o = 1; o < 8; o <<= 1) {
            int t = __shfl_up_sync(0xffu, ss, o);
            if (lane >= o) ss += t;
        }
        wsum[lane] = ss;
    }
    __syncthreads();
    int excl = s - v + (wid ? wsum[wid - 1] : 0) + g_bsum[blockIdx.x];
    if (i < N_NODES) {
        g_rowstart[i] = excl;
        g_wptr[i] = excl;
    }
}

__global__ void fill_kernel(const void* __restrict__ edge, int E) {
    int e = blockIdx.x * blockDim.x + threadIdx.x;
    if (e >= E) return;
    int is64 = g_idx64;
    int s = load_idx(edge, e, is64);
    int d = load_idx(edge, (size_t)E + e, is64);
    int pos = atomicAdd(&g_wptr[d], 1);
    g_csr[pos] = s;
}

// ---------------- layer-1 aggregate ----------------
__global__ __launch_bounds__(256) void agg1_kernel(const float* __restrict__ x) {
    int n = (int)(((size_t)blockIdx.x * blockDim.x + threadIdx.x) >> 5);
    if (n >= N_NODES) return;
    int lane = threadIdx.x & 31;
    int start = g_rowstart[n];
    int end = g_rowstart[n + 1];
    float4 acc0 = make_float4(0.f, 0.f, 0.f, 0.f);
    float4 acc1 = make_float4(0.f, 0.f, 0.f, 0.f);
    int e = start;
    for (; e + 1 < end; e += 2) {
        int s0 = g_csr[e];
        int s1 = g_csr[e + 1];
        float4 v0 = reinterpret_cast<const float4*>(x + (size_t)s0 * F_IN)[lane];
        float4 v1 = reinterpret_cast<const float4*>(x + (size_t)s1 * F_IN)[lane];
        acc0.x += v0.x; acc0.y += v0.y; acc0.z += v0.z; acc0.w += v0.w;
        acc1.x += v1.x; acc1.y += v1.y; acc1.z += v1.z; acc1.w += v1.w;
    }
    if (e < end) {
        int s0 = g_csr[e];
        float4 v0 = reinterpret_cast<const float4*>(x + (size_t)s0 * F_IN)[lane];
        acc0.x += v0.x; acc0.y += v0.y; acc0.z += v0.z; acc0.w += v0.w;
    }
    float r = 1.0f / fmaxf((float)(end - start), 1.0f);
    float4 o;
    o.x = (acc0.x + acc1.x) * r;
    o.y = (acc0.y + acc1.y) * r;
    o.z = (acc0.z + acc1.z) * r;
    o.w = (acc0.w + acc1.w) * r;
    reinterpret_cast<float4*>(g_agg1 + (size_t)n * F_IN)[lane] = o;
}

// ---------------- layer-2 aggregate ----------------
__global__ __launch_bounds__(256) void agg2_kernel() {
    int n = (int)(((size_t)blockIdx.x * blockDim.x + threadIdx.x) >> 5);
    if (n >= N_NODES) return;
    int lane = threadIdx.x & 31;
    int start = g_rowstart[n];
    int end = g_rowstart[n + 1];
    float4 a0 = make_float4(0.f, 0.f, 0.f, 0.f);
    float4 a1 = make_float4(0.f, 0.f, 0.f, 0.f);
    for (int e = start; e < end; e++) {
        int s = g_csr[e];
        const float4* hp = reinterpret_cast<const float4*>(g_h1 + (size_t)s * HID);
        float4 v0 = hp[lane];
        float4 v1 = hp[lane + 32];
        a0.x += v0.x; a0.y += v0.y; a0.z += v0.z; a0.w += v0.w;
        a1.x += v1.x; a1.y += v1.y; a1.z += v1.z; a1.w += v1.w;
    }
    float r = 1.0f / fmaxf((float)(end - start), 1.0f);
    a0.x *= r; a0.y *= r; a0.z *= r; a0.w *= r;
    a1.x *= r; a1.y *= r; a1.z *= r; a1.w *= r;
    float4* op = reinterpret_cast<float4*>(g_agg2 + (size_t)n * HID);
    op[lane] = a0;
    op[lane + 32] = a1;
}

// ---------------- bf16x2 tensor-core dual GEMM + bias + relu ----------------
// C[M,256] = relu( A0@W0 + A1@W1 + bias ), fp32 emulated as bf16_hi/lo (3 mmas)
__device__ __forceinline__ void mma_bf16(float* c, const uint32_t* a, const uint32_t* b) {
    asm volatile(
        "mma.sync.aligned.m16n8k16.row.col.f32.bf16.bf16.f32 "
        "{%0,%1,%2,%3}, {%4,%5,%6,%7}, {%8,%9}, {%0,%1,%2,%3};"
        : "+f"(c[0]), "+f"(c[1]), "+f"(c[2]), "+f"(c[3])
        : "r"(a[0]), "r"(a[1]), "r"(a[2]), "r"(a[3]), "r"(b[0]), "r"(b[1]));
}

__global__ __launch_bounds__(256) void gemm_dual_bf16x2_kernel(
    const float* __restrict__ A0, int K0,
    const float* __restrict__ A1, int K1,
    const float* __restrict__ W0, const float* __restrict__ W1w,
    const float* __restrict__ bias, float* __restrict__ C, int M) {
    const int N = 256;
    const int SP = 40;  // smem row stride (bf16 elems): conflict-free for frag loads
    __shared__ __nv_bfloat16 Ah[128][SP];
    __shared__ __nv_bfloat16 Al[128][SP];
    __shared__ __nv_bfloat16 Bh[128][SP];
    __shared__ __nv_bfloat16 Bl[128][SP];

    int tid = threadIdx.x;
    int lane = tid & 31;
    int wid = tid >> 5;
    int bm = blockIdx.x * 128;
    int bn = blockIdx.y * 128;
    int wm = (wid >> 2) * 64;   // warp m offset (2 rows of warps)
    int wn = (wid & 3) * 32;    // warp n offset (4 cols of warps)

    float acc[4][4][4];
#pragma unroll
    for (int mi = 0; mi < 4; mi++)
#pragma unroll
        for (int ni = 0; ni < 4; ni++)
#pragma unroll
            for (int q = 0; q < 4; q++) acc[mi][ni][q] = 0.f;

    int arow = tid >> 1;             // 0..127
    int ak0 = (tid & 1) * 16;        // 0 / 16
    int bk = tid >> 3;               // 0..31
    int bn0 = (tid & 7) * 16;        // 0..112

    int g = lane >> 2;               // 0..7
    int tq = (lane & 3) * 2;         // 0,2,4,6

    int K = K0 + K1;
    for (int kt = 0; kt < K; kt += 32) {
        const float* Ap;
        const float* Wp;
        int lda, kloc;
        if (kt < K0) { Ap = A0; Wp = W0; lda = K0; kloc = kt; }
        else         { Ap = A1; Wp = W1w; lda = K1; kloc = kt - K0; }

        // load + split A tile [128 rows x 32 k]
        {
            int gr = bm + arow;
            const float4* srcp = (gr < M)
                ? reinterpret_cast<const float4*>(Ap + (size_t)gr * lda + kloc + ak0)
                : nullptr;
#pragma unroll
            for (int i = 0; i < 4; i++) {
                float4 v = srcp ? srcp[i] : make_float4(0.f, 0.f, 0.f, 0.f);
                float vv[4] = {v.x, v.y, v.z, v.w};
#pragma unroll
                for (int j = 0; j < 4; j++) {
                    __nv_bfloat16 hi = __float2bfloat16(vv[j]);
                    __nv_bfloat16 lo = __float2bfloat16(vv[j] - __bfloat162float(hi));
                    Ah[arow][ak0 + i * 4 + j] = hi;
                    Al[arow][ak0 + i * 4 + j] = lo;
                }
            }
        }
        // load + split + transpose B tile [32 k x 128 n] -> Bs[n][k]
        {
            const float4* wsrc = reinterpret_cast<const float4*>(Wp + (size_t)(kloc + bk) * N + bn + bn0);
#pragma unroll
            for (int i = 0; i < 4; i++) {
                float4 v = wsrc[i];
                float vv[4] = {v.x, v.y, v.z, v.w};
#pragma unroll
                for (int j = 0; j < 4; j++) {
                    __nv_bfloat16 hi = __float2bfloat16(vv[j]);
                    __nv_bfloat16 lo = __float2bfloat16(vv[j] - __bfloat162float(hi));
                    Bh[bn0 + i * 4 + j][bk] = hi;
                    Bl[bn0 + i * 4 + j][bk] = lo;
                }
            }
        }
        __syncthreads();

#pragma unroll
        for (int ks = 0; ks < 2; ks++) {
            int k0 = ks * 16;
            uint32_t afh[4][4], afl[4][4], bfh[4][2], bfl[4][2];
#pragma unroll
            for (int mi = 0; mi < 4; mi++) {
                int r0 = wm + mi * 16 + g;
                afh[mi][0] = *reinterpret_cast<const uint32_t*>(&Ah[r0][k0 + tq]);
                afh[mi][1] = *reinterpret_cast<const uint32_t*>(&Ah[r0 + 8][k0 + tq]);
                afh[mi][2] = *reinterpret_cast<const uint32_t*>(&Ah[r0][k0 + tq + 8]);
                afh[mi][3] = *reinterpret_cast<const uint32_t*>(&Ah[r0 + 8][k0 + tq + 8]);
                afl[mi][0] = *reinterpret_cast<const uint32_t*>(&Al[r0][k0 + tq]);
                afl[mi][1] = *reinterpret_cast<const uint32_t*>(&Al[r0 + 8][k0 + tq]);
                afl[mi][2] = *reinterpret_cast<const uint32_t*>(&Al[r0][k0 + tq + 8]);
                afl[mi][3] = *reinterpret_cast<const uint32_t*>(&Al[r0 + 8][k0 + tq + 8]);
            }
#pragma unroll
            for (int ni = 0; ni < 4; ni++) {
                int nn = wn + ni * 8 + g;
                bfh[ni][0] = *reinterpret_cast<const uint32_t*>(&Bh[nn][k0 + tq]);
                bfh[ni][1] = *reinterpret_cast<const uint32_t*>(&Bh[nn][k0 + tq + 8]);
                bfl[ni][0] = *reinterpret_cast<const uint32_t*>(&Bl[nn][k0 + tq]);
                bfl[ni][1] = *reinterpret_cast<const uint32_t*>(&Bl[nn][k0 + tq + 8]);
            }
#pragma unroll
            for (int mi = 0; mi < 4; mi++)
#pragma unroll
                for (int ni = 0; ni < 4; ni++) {
                    mma_bf16(acc[mi][ni], afh[mi], bfh[ni]);
                    mma_bf16(acc[mi][ni], afh[mi], bfl[ni]);
                    mma_bf16(acc[mi][ni], afl[mi], bfh[ni]);
                }
        }
        __syncthreads();
    }

    // epilogue: bias + relu, float2 stores
#pragma unroll
    for (int mi = 0; mi < 4; mi++) {
#pragma unroll
        for (int ni = 0; ni < 4; ni++) {
            int col = bn + wn + ni * 8 + tq;
            float bv0 = bias[col];
            float bv1 = bias[col + 1];
            int r0 = bm + wm + mi * 16 + g;
            if (r0 < M) {
                float2 o;
                o.x = fmaxf(acc[mi][ni][0] + bv0, 0.f);
                o.y = fmaxf(acc[mi][ni][1] + bv1, 0.f);
                *reinterpret_cast<float2*>(&C[(size_t)r0 * N + col]) = o;
            }
            int r1 = r0 + 8;
            if (r1 < M) {
                float2 o;
                o.x = fmaxf(acc[mi][ni][2] + bv0, 0.f);
                o.y = fmaxf(acc[mi][ni][3] + bv1, 0.f);
                *reinterpret_cast<float2*>(&C[(size_t)r1 * N + col]) = o;
            }
        }
    }
}

// ---------------- MLP head ----------------
__global__ __launch_bounds__(256) void mlp_kernel(
    const float* __restrict__ x_tab, const void* __restrict__ idx,
    const float* __restrict__ W1, const float* __restrict__ b1,
    const float* __restrict__ W2, const float* __restrict__ b2,
    const float* __restrict__ W3, const float* __restrict__ b3,
    float* __restrict__ out, int B) {
    __shared__ float zs[8][280];
    __shared__ float z1s[8][64];
    int w = threadIdx.x >> 5;
    int lane = threadIdx.x & 31;
    int row = blockIdx.x * 8 + w;
    if (row >= B) return;
    int node = load_idx(idx, row, g_idx64);
    const float4* h = reinterpret_cast<const float4*>(g_h2 + (size_t)node * HID);
    float4 v = h[lane];
    *reinterpret_cast<float4*>(&zs[w][lane * 4]) = v;
    v = h[lane + 32];
    *reinterpret_cast<float4*>(&zs[w][128 + lane * 4]) = v;
    if (lane < 16) zs[w][256 + lane] = x_tab[row * 16 + lane];
    __syncwarp();

    float a0 = b1[lane];
    float a1 = b1[lane + 32];
#pragma unroll 4
    for (int k = 0; k < 272; k++) {
        float zk = zs[w][k];
        a0 += zk * W1[k * 64 + lane];
        a1 += zk * W1[k * 64 + lane + 32];
    }
    z1s[w][lane] = fmaxf(a0, 0.f);
    z1s[w][lane + 32] = fmaxf(a1, 0.f);
    __syncwarp();

    float a = b2[lane];
#pragma unroll
    for (int k = 0; k < 64; k++) a += z1s[w][k] * W2[k * 32 + lane];
    float z2 = fmaxf(a, 0.f);

    float p = z2 * W3[lane];
#pragma unroll
    for (int off = 16; off; off >>= 1) p += __shfl_down_sync(0xffffffffu, p, off);
    if (lane == 0) out[row] = p + b3[0];
}

// ---------------- launch ----------------
extern "C" void kernel_launch(void* const* d_in, const int* in_sizes, int n_in,
                              void* d_out, int out_size) {
    const float* x     = (const float*)d_in[0];
    const void* edge   = d_in[1];
    const void* idxb   = d_in[2];
    const float* x_tab = (const float*)d_in[3];
    const float* Wl1 = (const float*)d_in[4];
    const float* bl1 = (const float*)d_in[5];
    const float* Wr1 = (const float*)d_in[6];
    const float* Wl2 = (const float*)d_in[7];
    const float* bl2 = (const float*)d_in[8];
    const float* Wr2 = (const float*)d_in[9];
    const float* W1  = (const float*)d_in[10];
    const float* b1  = (const float*)d_in[11];
    const float* W2  = (const float*)d_in[12];
    const float* b2  = (const float*)d_in[13];
    const float* W3  = (const float*)d_in[14];
    const float* b3  = (const float*)d_in[15];
    float* out = (float*)d_out;

    int E = in_sizes[1] / 2;
    if (E > E_MAX) E = E_MAX;
    int B = in_sizes[2];

    float *p_agg1, *p_agg2, *p_h1, *p_h2;
    cudaGetSymbolAddress((void**)&p_agg1, g_agg1);
    cudaGetSymbolAddress((void**)&p_agg2, g_agg2);
    cudaGetSymbolAddress((void**)&p_h1, g_h1);
    cudaGetSymbolAddress((void**)&p_h2, g_h2);

    // 0. index dtype sniff
    sniff_kernel<<<1, 32>>>((const int*)edge);

    // 1. CSR build (hierarchical scan)
    zero_deg_kernel<<<NBLK_SCAN, 256>>>();
    degree_kernel<<<(E + 255) / 256, 256>>>(edge, E);
    blocksum_kernel<<<NBLK_SCAN, 256>>>();
    scan_bsum_kernel<<<1, 512>>>(E);
    distribute_kernel<<<NBLK_SCAN, 256>>>();
    fill_kernel<<<(E + 255) / 256, 256>>>(edge, E);

    // 2. layer-1 mean aggregate
    agg1_kernel<<<(N_NODES * 32 + 255) / 256, 256>>>(x);

    // 3. h1 = relu(mean1 @ Wl1 + x @ Wr1 + bl1)   [tensor core]
    {
        dim3 grid((N_NODES + 127) / 128, 2);
        gemm_dual_bf16x2_kernel<<<grid, 256>>>(p_agg1, F_IN, x, F_IN, Wl1, Wr1, bl1, p_h1, N_NODES);
    }

    // 4. layer-2 mean aggregate
    agg2_kernel<<<(N_NODES * 32 + 255) / 256, 256>>>();

    // 5. h2 = relu(mean2 @ Wl2 + h1 @ Wr2 + bl2)  [tensor core]
    {
        dim3 grid((N_NODES + 127) / 128, 2);
        gemm_dual_bf16x2_kernel<<<grid, 256>>>(p_agg2, HID, p_h1, HID, Wl2, Wr2, bl2, p_h2, N_NODES);
    }

    // 6. MLP head
    mlp_kernel<<<(B + 7) / 8, 256>>>(x_tab, idxb, W1, b1, W2, b2, W3, b3, out, B);
}

// round 5
// speedup vs baseline: 2.9952x; 1.2461x over previous
#include <cuda_runtime.h>
#include <cuda_bf16.h>
#include <cstdint>
#include <cstddef>

#define N_NODES 100000
#define F_IN 128
#define HID 256
#define E_MAX 1600000
#define NBLK_SCAN ((N_NODES + 255) / 256)

// ---------------- scratch (device globals; no allocation allowed) ----------------
__device__ int g_idx64;
__device__ int g_deg[N_NODES];
__device__ int g_bsum[NBLK_SCAN + 1];
__device__ int g_rowstart[N_NODES + 1];
__device__ int g_wptr[N_NODES];
__device__ int g_csr[E_MAX];

__device__ __nv_bfloat16 g_xh[(size_t)N_NODES * F_IN];
__device__ __nv_bfloat16 g_xl[(size_t)N_NODES * F_IN];
__device__ __nv_bfloat16 g_a1h[(size_t)N_NODES * F_IN];
__device__ __nv_bfloat16 g_a1l[(size_t)N_NODES * F_IN];
__device__ float         g_h1[(size_t)N_NODES * HID];
__device__ __nv_bfloat16 g_h1h[(size_t)N_NODES * HID];
__device__ __nv_bfloat16 g_h1l[(size_t)N_NODES * HID];
__device__ __nv_bfloat16 g_a2h[(size_t)N_NODES * HID];
__device__ __nv_bfloat16 g_a2l[(size_t)N_NODES * HID];
__device__ float         g_h2[(size_t)N_NODES * HID];

// transposed split weights: [N=256][K]
__device__ __nv_bfloat16 g_wl1h[256 * F_IN], g_wl1l[256 * F_IN];
__device__ __nv_bfloat16 g_wr1h[256 * F_IN], g_wr1l[256 * F_IN];
__device__ __nv_bfloat16 g_wl2h[256 * HID], g_wl2l[256 * HID];
__device__ __nv_bfloat16 g_wr2h[256 * HID], g_wr2l[256 * HID];

// ---------------- helpers ----------------
__device__ __forceinline__ void split1(float v, __nv_bfloat16& h, __nv_bfloat16& l) {
    h = __float2bfloat16(v);
    l = __float2bfloat16(v - __bfloat162float(h));
}

__device__ __forceinline__ void split_store4(float4 v, __nv_bfloat16* ph, __nv_bfloat16* pl) {
    __nv_bfloat16 h0, h1, h2, h3, l0, l1, l2, l3;
    split1(v.x, h0, l0); split1(v.y, h1, l1);
    split1(v.z, h2, l2); split1(v.w, h3, l3);
    __nv_bfloat162* H = reinterpret_cast<__nv_bfloat162*>(ph);
    __nv_bfloat162* L = reinterpret_cast<__nv_bfloat162*>(pl);
    H[0] = __halves2bfloat162(h0, h1);
    H[1] = __halves2bfloat162(h2, h3);
    L[0] = __halves2bfloat162(l0, l1);
    L[1] = __halves2bfloat162(l2, l3);
}

// ---------------- index dtype sniff ----------------
__global__ void sniff_kernel(const int* __restrict__ e) {
    if (threadIdx.x == 0 && blockIdx.x == 0) {
        int allz = 1;
        for (int i = 0; i < 64; i++)
            if (e[2 * i + 1] != 0) { allz = 0; break; }
        g_idx64 = allz;
    }
}

__device__ __forceinline__ int load_idx(const void* __restrict__ p, size_t i, int is64) {
    if (is64) return (int)((const long long*)p)[i];
    return ((const int*)p)[i];
}

// ---------------- CSR build ----------------
__global__ void zero_deg_kernel() {
    int i = blockIdx.x * blockDim.x + threadIdx.x;
    if (i < N_NODES) g_deg[i] = 0;
}

__global__ void degree_kernel(const void* __restrict__ edge, int E) {
    int e = blockIdx.x * blockDim.x + threadIdx.x;
    if (e >= E) return;
    int d = load_idx(edge, (size_t)E + e, g_idx64);
    atomicAdd(&g_deg[d], 1);
}

__global__ void blocksum_kernel() {
    __shared__ int ws[8];
    int i = blockIdx.x * 256 + threadIdx.x;
    int v = (i < N_NODES) ? g_deg[i] : 0;
    int lane = threadIdx.x & 31, wid = threadIdx.x >> 5;
#pragma unroll
    for (int o = 16; o; o >>= 1) v += __shfl_down_sync(0xffffffffu, v, o);
    if (lane == 0) ws[wid] = v;
    __syncthreads();
    if (threadIdx.x == 0) {
        int s = 0;
#pragma unroll
        for (int k = 0; k < 8; k++) s += ws[k];
        g_bsum[blockIdx.x] = s;
    }
}

__global__ __launch_bounds__(512) void scan_bsum_kernel(int E) {
    __shared__ int wsum[16];
    int tid = threadIdx.x, lane = tid & 31, wid = tid >> 5;
    int v = (tid < NBLK_SCAN) ? g_bsum[tid] : 0;
    int s = v;
#pragma unroll
    for (int o = 1; o < 32; o <<= 1) {
        int t = __shfl_up_sync(0xffffffffu, s, o);
        if (lane >= o) s += t;
    }
    if (lane == 31) wsum[wid] = s;
    __syncthreads();
    if (wid == 0 && lane < 16) {
        int ws = wsum[lane];
        int ss = ws;
#pragma unroll
        for (int o = 1; o < 16; o <<= 1) {
            int t = __shfl_up_sync(0xffffu, ss, o);
            if (lane >= o) ss += t;
        }
        wsum[lane] = ss;
    }
    __syncthreads();
    int excl = s - v + (wid ? wsum[wid - 1] : 0);
    if (tid < NBLK_SCAN) g_bsum[tid] = excl;
    if (tid == 0) g_rowstart[N_NODES] = E;
}

__global__ void distribute_kernel() {
    __shared__ int wsum[8];
    int tid = threadIdx.x, lane = tid & 31, wid = tid >> 5;
    int i = blockIdx.x * 256 + tid;
    int v = (i < N_NODES) ? g_deg[i] : 0;
    int s = v;
#pragma unroll
    for (int o = 1; o < 32; o <<= 1) {
        int t = __shfl_up_sync(0xffffffffu, s, o);
        if (lane >= o) s += t;
    }
    if (lane == 31) wsum[wid] = s;
    __syncthreads();
    if (wid == 0 && lane < 8) {
        int ws = wsum[lane];
        int ss = ws;
#pragma unroll
        for (int o = 1; o < 8; o <<= 1) {
            int t = __shfl_up_sync(0xffu, ss, o);
            if (lane >= o) ss += t;
        }
        wsum[lane] = ss;
    }
    __syncthreads();
    int excl = s - v + (wid ? wsum[wid - 1] : 0) + g_bsum[blockIdx.x];
    if (i < N_NODES) {
        g_rowstart[i] = excl;
        g_wptr[i] = excl;
    }
}

__global__ void fill_kernel(const void* __restrict__ edge, int E) {
    int e = blockIdx.x * blockDim.x + threadIdx.x;
    if (e >= E) return;
    int is64 = g_idx64;
    int s = load_idx(edge, e, is64);
    int d = load_idx(edge, (size_t)E + e, is64);
    int pos = atomicAdd(&g_wptr[d], 1);
    g_csr[pos] = s;
}

// ---------------- splits ----------------
__global__ void split_x_kernel(const float* __restrict__ x) {
    size_t i = (size_t)blockIdx.x * blockDim.x + threadIdx.x;
    const size_t n4 = (size_t)N_NODES * F_IN / 4;
    if (i >= n4) return;
    float4 v = reinterpret_cast<const float4*>(x)[i];
    split_store4(v, g_xh + i * 4, g_xl + i * 4);
}

// W[k][256] -> Th/Tl[n][K]
__global__ void split_w_kernel(const float* __restrict__ W,
                               __nv_bfloat16* __restrict__ Th,
                               __nv_bfloat16* __restrict__ Tl, int K) {
    int idx = blockIdx.x * blockDim.x + threadIdx.x;
    if (idx >= K * 256) return;
    int k = idx >> 8;
    int n = idx & 255;
    __nv_bfloat16 h, l;
    split1(W[idx], h, l);
    Th[n * K + k] = h;
    Tl[n * K + k] = l;
}

// ---------------- layer-1 aggregate -> bf16 hi/lo directly ----------------
__global__ __launch_bounds__(256) void agg1_kernel(const float* __restrict__ x) {
    int n = (int)(((size_t)blockIdx.x * blockDim.x + threadIdx.x) >> 5);
    if (n >= N_NODES) return;
    int lane = threadIdx.x & 31;
    int start = g_rowstart[n];
    int end = g_rowstart[n + 1];
    float4 acc0 = make_float4(0.f, 0.f, 0.f, 0.f);
    float4 acc1 = make_float4(0.f, 0.f, 0.f, 0.f);
    int e = start;
    for (; e + 1 < end; e += 2) {
        int s0 = g_csr[e];
        int s1 = g_csr[e + 1];
        float4 v0 = reinterpret_cast<const float4*>(x + (size_t)s0 * F_IN)[lane];
        float4 v1 = reinterpret_cast<const float4*>(x + (size_t)s1 * F_IN)[lane];
        acc0.x += v0.x; acc0.y += v0.y; acc0.z += v0.z; acc0.w += v0.w;
        acc1.x += v1.x; acc1.y += v1.y; acc1.z += v1.z; acc1.w += v1.w;
    }
    if (e < end) {
        int s0 = g_csr[e];
        float4 v0 = reinterpret_cast<const float4*>(x + (size_t)s0 * F_IN)[lane];
        acc0.x += v0.x; acc0.y += v0.y; acc0.z += v0.z; acc0.w += v0.w;
    }
    float r = 1.0f / fmaxf((float)(end - start), 1.0f);
    float4 o;
    o.x = (acc0.x + acc1.x) * r;
    o.y = (acc0.y + acc1.y) * r;
    o.z = (acc0.z + acc1.z) * r;
    o.w = (acc0.w + acc1.w) * r;
    size_t off = (size_t)n * F_IN + lane * 4;
    split_store4(o, g_a1h + off, g_a1l + off);
}

// ---------------- layer-2 aggregate -> bf16 hi/lo directly ----------------
__global__ __launch_bounds__(256) void agg2_kernel() {
    int n = (int)(((size_t)blockIdx.x * blockDim.x + threadIdx.x) >> 5);
    if (n >= N_NODES) return;
    int lane = threadIdx.x & 31;
    int start = g_rowstart[n];
    int end = g_rowstart[n + 1];
    float4 a0 = make_float4(0.f, 0.f, 0.f, 0.f);
    float4 a1 = make_float4(0.f, 0.f, 0.f, 0.f);
    for (int e = start; e < end; e++) {
        int s = g_csr[e];
        const float4* hp = reinterpret_cast<const float4*>(g_h1 + (size_t)s * HID);
        float4 v0 = hp[lane];
        float4 v1 = hp[lane + 32];
        a0.x += v0.x; a0.y += v0.y; a0.z += v0.z; a0.w += v0.w;
        a1.x += v1.x; a1.y += v1.y; a1.z += v1.z; a1.w += v1.w;
    }
    float r = 1.0f / fmaxf((float)(end - start), 1.0f);
    a0.x *= r; a0.y *= r; a0.z *= r; a0.w *= r;
    a1.x *= r; a1.y *= r; a1.z *= r; a1.w *= r;
    size_t off = (size_t)n * HID;
    split_store4(a0, g_a2h + off + lane * 4, g_a2l + off + lane * 4);
    split_store4(a1, g_a2h + off + 128 + lane * 4, g_a2l + off + 128 + lane * 4);
}

// ---------------- bf16x2 tensor-core dual GEMM (pre-split operands) ----------------
__device__ __forceinline__ void mma_bf16(float* c, const uint32_t* a, const uint32_t* b) {
    asm volatile(
        "mma.sync.aligned.m16n8k16.row.col.f32.bf16.bf16.f32 "
        "{%0,%1,%2,%3}, {%4,%5,%6,%7}, {%8,%9}, {%0,%1,%2,%3};"
        : "+f"(c[0]), "+f"(c[1]), "+f"(c[2]), "+f"(c[3])
        : "r"(a[0]), "r"(a[1]), "r"(a[2]), "r"(a[3]), "r"(b[0]), "r"(b[1]));
}

__device__ __forceinline__ void st_smem32(__nv_bfloat16* dst, const uint4* r) {
    float2* d = reinterpret_cast<float2*>(dst);
    d[0] = make_float2(__uint_as_float(r[0].x), __uint_as_float(r[0].y));
    d[1] = make_float2(__uint_as_float(r[0].z), __uint_as_float(r[0].w));
    d[2] = make_float2(__uint_as_float(r[1].x), __uint_as_float(r[1].y));
    d[3] = make_float2(__uint_as_float(r[1].z), __uint_as_float(r[1].w));
}

// C[M,256] = relu( A0@B0^T + A1@B1^T + bias ); A*,B* pre-split bf16 hi/lo.
// B is [256][K] (pre-transposed). Optionally writes bf16 split of C.
__global__ __launch_bounds__(256) void gemm_dual_pre_kernel(
    const __nv_bfloat16* __restrict__ A0h, const __nv_bfloat16* __restrict__ A0l, int K0,
    const __nv_bfloat16* __restrict__ A1h, const __nv_bfloat16* __restrict__ A1l, int K1,
    const __nv_bfloat16* __restrict__ B0h, const __nv_bfloat16* __restrict__ B0l,
    const __nv_bfloat16* __restrict__ B1h, const __nv_bfloat16* __restrict__ B1l,
    const float* __restrict__ bias, float* __restrict__ C,
    __nv_bfloat16* __restrict__ Ch, __nv_bfloat16* __restrict__ Cl, int M) {
    const int N = 256;
    const int SP = 40;
    __shared__ __nv_bfloat16 Ah[128][SP];
    __shared__ __nv_bfloat16 Al[128][SP];
    __shared__ __nv_bfloat16 Bh[128][SP];
    __shared__ __nv_bfloat16 Bl[128][SP];

    int tid = threadIdx.x;
    int lane = tid & 31;
    int wid = tid >> 5;
    int bm = blockIdx.x * 128;
    int bn = blockIdx.y * 128;
    int wm = (wid >> 2) * 64;
    int wn = (wid & 3) * 32;

    float acc[4][4][4];
#pragma unroll
    for (int mi = 0; mi < 4; mi++)
#pragma unroll
        for (int ni = 0; ni < 4; ni++)
#pragma unroll
            for (int q = 0; q < 4; q++) acc[mi][ni][q] = 0.f;

    int arow = tid >> 1;            // 0..127
    int ak0 = (tid & 1) * 16;       // 0/16  (elems)
    int brow = tid >> 1;            // 0..127
    int bk0 = (tid & 1) * 16;

    int g = lane >> 2;
    int tq = (lane & 3) * 2;

    int K = K0 + K1;
    uint4 rah[2], ral[2], rbh[2], rbl[2];

    auto gload = [&](int kt) {
        const __nv_bfloat16 *pah, *pal, *pbh, *pbl;
        int lda, kloc;
        if (kt < K0) { pah = A0h; pal = A0l; pbh = B0h; pbl = B0l; lda = K0; kloc = kt; }
        else         { pah = A1h; pal = A1l; pbh = B1h; pbl = B1l; lda = K1; kloc = kt - K0; }
        int gr = bm + arow;
        if (gr < M) {
            const uint4* p = reinterpret_cast<const uint4*>(pah + (size_t)gr * lda + kloc + ak0);
            rah[0] = p[0]; rah[1] = p[1];
            const uint4* q = reinterpret_cast<const uint4*>(pal + (size_t)gr * lda + kloc + ak0);
            ral[0] = q[0]; ral[1] = q[1];
        } else {
            rah[0] = rah[1] = ral[0] = ral[1] = make_uint4(0, 0, 0, 0);
        }
        const uint4* pb = reinterpret_cast<const uint4*>(pbh + (size_t)(bn + brow) * lda + kloc + bk0);
        rbh[0] = pb[0]; rbh[1] = pb[1];
        const uint4* qb = reinterpret_cast<const uint4*>(pbl + (size_t)(bn + brow) * lda + kloc + bk0);
        rbl[0] = qb[0]; rbl[1] = qb[1];
    };
    auto sstore = [&]() {
        st_smem32(&Ah[arow][ak0], rah);
        st_smem32(&Al[arow][ak0], ral);
        st_smem32(&Bh[brow][bk0], rbh);
        st_smem32(&Bl[brow][bk0], rbl);
    };

    gload(0);
    sstore();
    __syncthreads();

    for (int kt = 0; kt < K; kt += 32) {
        bool more = (kt + 32) < K;
        if (more) gload(kt + 32);

#pragma unroll
        for (int ks = 0; ks < 2; ks++) {
            int k0 = ks * 16;
            uint32_t afh[4][4], afl[4][4], bfh[4][2], bfl[4][2];
#pragma unroll
            for (int mi = 0; mi < 4; mi++) {
                int r0 = wm + mi * 16 + g;
                afh[mi][0] = *reinterpret_cast<const uint32_t*>(&Ah[r0][k0 + tq]);
                afh[mi][1] = *reinterpret_cast<const uint32_t*>(&Ah[r0 + 8][k0 + tq]);
                afh[mi][2] = *reinterpret_cast<const uint32_t*>(&Ah[r0][k0 + tq + 8]);
                afh[mi][3] = *reinterpret_cast<const uint32_t*>(&Ah[r0 + 8][k0 + tq + 8]);
                afl[mi][0] = *reinterpret_cast<const uint32_t*>(&Al[r0][k0 + tq]);
                afl[mi][1] = *reinterpret_cast<const uint32_t*>(&Al[r0 + 8][k0 + tq]);
                afl[mi][2] = *reinterpret_cast<const uint32_t*>(&Al[r0][k0 + tq + 8]);
                afl[mi][3] = *reinterpret_cast<const uint32_t*>(&Al[r0 + 8][k0 + tq + 8]);
            }
#pragma unroll
            for (int ni = 0; ni < 4; ni++) {
                int nn = wn + ni * 8 + g;
                bfh[ni][0] = *reinterpret_cast<const uint32_t*>(&Bh[nn][k0 + tq]);
                bfh[ni][1] = *reinterpret_cast<const uint32_t*>(&Bh[nn][k0 + tq + 8]);
                bfl[ni][0] = *reinterpret_cast<const uint32_t*>(&Bl[nn][k0 + tq]);
                bfl[ni][1] = *reinterpret_cast<const uint32_t*>(&Bl[nn][k0 + tq + 8]);
            }
#pragma unroll
            for (int mi = 0; mi < 4; mi++)
#pragma unroll
                for (int ni = 0; ni < 4; ni++) {
                    mma_bf16(acc[mi][ni], afh[mi], bfh[ni]);
                    mma_bf16(acc[mi][ni], afh[mi], bfl[ni]);
                    mma_bf16(acc[mi][ni], afl[mi], bfh[ni]);
                }
        }
        if (more) {
            __syncthreads();
            sstore();
            __syncthreads();
        }
    }

    // epilogue: bias + relu (+ optional bf16 split)
#pragma unroll
    for (int mi = 0; mi < 4; mi++) {
#pragma unroll
        for (int ni = 0; ni < 4; ni++) {
            int col = bn + wn + ni * 8 + tq;
            float bv0 = bias[col];
            float bv1 = bias[col + 1];
#pragma unroll
            for (int h = 0; h < 2; h++) {
                int r = bm + wm + mi * 16 + g + h * 8;
                if (r < M) {
                    float v0 = fmaxf(acc[mi][ni][h * 2 + 0] + bv0, 0.f);
                    float v1 = fmaxf(acc[mi][ni][h * 2 + 1] + bv1, 0.f);
                    *reinterpret_cast<float2*>(&C[(size_t)r * N + col]) = make_float2(v0, v1);
                    if (Ch) {
                        __nv_bfloat16 h0, h1, l0, l1;
                        split1(v0, h0, l0);
                        split1(v1, h1, l1);
                        *reinterpret_cast<__nv_bfloat162*>(&Ch[(size_t)r * N + col]) = __halves2bfloat162(h0, h1);
                        *reinterpret_cast<__nv_bfloat162*>(&Cl[(size_t)r * N + col]) = __halves2bfloat162(l0, l1);
                    }
                }
            }
        }
    }
}

// ---------------- MLP head ----------------
__global__ __launch_bounds__(256) void mlp_kernel(
    const float* __restrict__ x_tab, const void* __restrict__ idx,
    const float* __restrict__ W1, const float* __restrict__ b1,
    const float* __restrict__ W2, const float* __restrict__ b2,
    const float* __restrict__ W3, const float* __restrict__ b3,
    float* __restrict__ out, int B) {
    __shared__ float zs[8][280];
    __shared__ float z1s[8][64];
    int w = threadIdx.x >> 5;
    int lane = threadIdx.x & 31;
    int row = blockIdx.x * 8 + w;
    if (row >= B) return;
    int node = load_idx(idx, row, g_idx64);
    const float4* h = reinterpret_cast<const float4*>(g_h2 + (size_t)node * HID);
    float4 v = h[lane];
    *reinterpret_cast<float4*>(&zs[w][lane * 4]) = v;
    v = h[lane + 32];
    *reinterpret_cast<float4*>(&zs[w][128 + lane * 4]) = v;
    if (lane < 16) zs[w][256 + lane] = x_tab[row * 16 + lane];
    __syncwarp();

    float a0 = b1[lane];
    float a1 = b1[lane + 32];
#pragma unroll 4
    for (int k = 0; k < 272; k++) {
        float zk = zs[w][k];
        a0 += zk * W1[k * 64 + lane];
        a1 += zk * W1[k * 64 + lane + 32];
    }
    z1s[w][lane] = fmaxf(a0, 0.f);
    z1s[w][lane + 32] = fmaxf(a1, 0.f);
    __syncwarp();

    float a = b2[lane];
#pragma unroll
    for (int k = 0; k < 64; k++) a += z1s[w][k] * W2[k * 32 + lane];
    float z2 = fmaxf(a, 0.f);

    float p = z2 * W3[lane];
#pragma unroll
    for (int off = 16; off; off >>= 1) p += __shfl_down_sync(0xffffffffu, p, off);
    if (lane == 0) out[row] = p + b3[0];
}

// ---------------- launch ----------------
extern "C" void kernel_launch(void* const* d_in, const int* in_sizes, int n_in,
                              void* d_out, int out_size) {
    const float* x     = (const float*)d_in[0];
    const void* edge   = d_in[1];
    const void* idxb   = d_in[2];
    const float* x_tab = (const float*)d_in[3];
    const float* Wl1 = (const float*)d_in[4];
    const float* bl1 = (const float*)d_in[5];
    const float* Wr1 = (const float*)d_in[6];
    const float* Wl2 = (const float*)d_in[7];
    const float* bl2 = (const float*)d_in[8];
    const float* Wr2 = (const float*)d_in[9];
    const float* W1  = (const float*)d_in[10];
    const float* b1  = (const float*)d_in[11];
    const float* W2  = (const float*)d_in[12];
    const float* b2  = (const float*)d_in[13];
    const float* W3  = (const float*)d_in[14];
    const float* b3  = (const float*)d_in[15];
    float* out = (float*)d_out;

    int E = in_sizes[1] / 2;
    if (E > E_MAX) E = E_MAX;
    int B = in_sizes[2];

    __nv_bfloat16 *p_xh, *p_xl, *p_a1h, *p_a1l, *p_h1h, *p_h1l, *p_a2h, *p_a2l;
    __nv_bfloat16 *p_wl1h, *p_wl1l, *p_wr1h, *p_wr1l, *p_wl2h, *p_wl2l, *p_wr2h, *p_wr2l;
    float *p_h1, *p_h2;
    cudaGetSymbolAddress((void**)&p_xh, g_xh);
    cudaGetSymbolAddress((void**)&p_xl, g_xl);
    cudaGetSymbolAddress((void**)&p_a1h, g_a1h);
    cudaGetSymbolAddress((void**)&p_a1l, g_a1l);
    cudaGetSymbolAddress((void**)&p_h1, g_h1);
    cudaGetSymbolAddress((void**)&p_h1h, g_h1h);
    cudaGetSymbolAddress((void**)&p_h1l, g_h1l);
    cudaGetSymbolAddress((void**)&p_a2h, g_a2h);
    cudaGetSymbolAddress((void**)&p_a2l, g_a2l);
    cudaGetSymbolAddress((void**)&p_h2, g_h2);
    cudaGetSymbolAddress((void**)&p_wl1h, g_wl1h);
    cudaGetSymbolAddress((void**)&p_wl1l, g_wl1l);
    cudaGetSymbolAddress((void**)&p_wr1h, g_wr1h);
    cudaGetSymbolAddress((void**)&p_wr1l, g_wr1l);
    cudaGetSymbolAddress((void**)&p_wl2h, g_wl2h);
    cudaGetSymbolAddress((void**)&p_wl2l, g_wl2l);
    cudaGetSymbolAddress((void**)&p_wr2h, g_wr2h);
    cudaGetSymbolAddress((void**)&p_wr2l, g_wr2l);

    // 0. index dtype sniff
    sniff_kernel<<<1, 32>>>((const int*)edge);

    // 1. CSR build
    zero_deg_kernel<<<NBLK_SCAN, 256>>>();
    degree_kernel<<<(E + 255) / 256, 256>>>(edge, E);
    blocksum_kernel<<<NBLK_SCAN, 256>>>();
    scan_bsum_kernel<<<1, 512>>>(E);
    distribute_kernel<<<NBLK_SCAN, 256>>>();
    fill_kernel<<<(E + 255) / 256, 256>>>(edge, E);

    // 2. pre-split x and weights
    {
        size_t n4 = (size_t)N_NODES * F_IN / 4;
        split_x_kernel<<<(int)((n4 + 255) / 256), 256>>>(x);
        split_w_kernel<<<(F_IN * 256 + 255) / 256, 256>>>(Wl1, p_wl1h, p_wl1l, F_IN);
        split_w_kernel<<<(F_IN * 256 + 255) / 256, 256>>>(Wr1, p_wr1h, p_wr1l, F_IN);
        split_w_kernel<<<(HID * 256 + 255) / 256, 256>>>(Wl2, p_wl2h, p_wl2l, HID);
        split_w_kernel<<<(HID * 256 + 255) / 256, 256>>>(Wr2, p_wr2h, p_wr2l, HID);
    }

    // 3. layer-1 mean aggregate (writes bf16 split)
    agg1_kernel<<<(N_NODES * 32 + 255) / 256, 256>>>(x);

    // 4. h1 = relu(mean1 @ Wl1 + x @ Wr1 + bl1)
    {
        dim3 grid((N_NODES + 127) / 128, 2);
        gemm_dual_pre_kernel<<<grid, 256>>>(
            p_a1h, p_a1l, F_IN, p_xh, p_xl, F_IN,
            p_wl1h, p_wl1l, p_wr1h, p_wr1l,
            bl1, p_h1, p_h1h, p_h1l, N_NODES);
    }

    // 5. layer-2 mean aggregate (writes bf16 split)
    agg2_kernel<<<(N_NODES * 32 + 255) / 256, 256>>>();

    // 6. h2 = relu(mean2 @ Wl2 + h1 @ Wr2 + bl2)
    {
        dim3 grid((N_NODES + 127) / 128, 2);
        gemm_dual_pre_kernel<<<grid, 256>>>(
            p_a2h, p_a2l, HID, p_h1h, p_h1l, HID,
            p_wl2h, p_wl2l, p_wr2h, p_wr2l,
            bl2, p_h2, (\
__nv_bfloat16*)nullptr, (__nv_bfloat16*)nullptr, N_NODES);
    }

    // 7. MLP head
    mlp_kernel<<<(B + 7) / 8, 256>>>(x_tab, idxb, W1, b1, W2, b2, W3, b3, out, B);
}

// round 7
// speedup vs baseline: 5.4139x; 1.8075x over previous
#include <cuda_runtime.h>
#include <cuda_bf16.h>
#include <cstdint>
#include <cstddef>

#define N_NODES 100000
#define F_IN 128
#define HID 256
#define E_MAX 1600000
#define B_MAX 16384
#define NBLK_SCAN ((N_NODES + 255) / 256)

// ---------------- scratch (device globals; no allocation allowed) ----------------
__device__ int g_idx64;
__device__ int g_deg[N_NODES];
__device__ int g_bsum[NBLK_SCAN + 1];
__device__ int g_rowstart[N_NODES + 1];
__device__ int g_wptr[N_NODES];
__device__ int g_csr[E_MAX];

// batch-node selection
__device__ int g_mark[N_NODES];
__device__ int g_node2slot[N_NODES];
__device__ int g_sel[B_MAX];
__device__ int g_nsel;

__device__ __nv_bfloat16 g_xh[(size_t)N_NODES * F_IN];
__device__ __nv_bfloat16 g_xl[(size_t)N_NODES * F_IN];
__device__ __nv_bfloat16 g_a1h[(size_t)N_NODES * F_IN];
__device__ __nv_bfloat16 g_a1l[(size_t)N_NODES * F_IN];
__device__ float         g_h1[(size_t)N_NODES * HID];
// compacted (selected nodes only)
__device__ __nv_bfloat16 g_h1ch[(size_t)B_MAX * HID];
__device__ __nv_bfloat16 g_h1cl[(size_t)B_MAX * HID];
__device__ __nv_bfloat16 g_a2h[(size_t)B_MAX * HID];
__device__ __nv_bfloat16 g_a2l[(size_t)B_MAX * HID];
__device__ float         g_h2c[(size_t)B_MAX * HID];

// transposed split weights: [N=256][K]
__device__ __nv_bfloat16 g_wl1h[256 * F_IN], g_wl1l[256 * F_IN];
__device__ __nv_bfloat16 g_wr1h[256 * F_IN], g_wr1l[256 * F_IN];
__device__ __nv_bfloat16 g_wl2h[256 * HID], g_wl2l[256 * HID];
__device__ __nv_bfloat16 g_wr2h[256 * HID], g_wr2l[256 * HID];

// ---------------- helpers ----------------
__device__ __forceinline__ void split1(float v, __nv_bfloat16& h, __nv_bfloat16& l) {
    h = __float2bfloat16(v);
    l = __float2bfloat16(v - __bfloat162float(h));
}

__device__ __forceinline__ void split_store4(float4 v, __nv_bfloat16* ph, __nv_bfloat16* pl) {
    __nv_bfloat16 h0, h1, h2, h3, l0, l1, l2, l3;
    split1(v.x, h0, l0); split1(v.y, h1, l1);
    split1(v.z, h2, l2); split1(v.w, h3, l3);
    __nv_bfloat162* H = reinterpret_cast<__nv_bfloat162*>(ph);
    __nv_bfloat162* L = reinterpret_cast<__nv_bfloat162*>(pl);
    H[0] = __halves2bfloat162(h0, h1);
    H[1] = __halves2bfloat162(h2, h3);
    L[0] = __halves2bfloat162(l0, l1);
    L[1] = __halves2bfloat162(l2, l3);
}

// ---------------- index dtype sniff ----------------
__global__ void sniff_kernel(const int* __restrict__ e) {
    if (threadIdx.x == 0 && blockIdx.x == 0) {
        int allz = 1;
        for (int i = 0; i < 64; i++)
            if (e[2 * i + 1] != 0) { allz = 0; break; }
        g_idx64 = allz;
    }
}

__device__ __forceinline__ int load_idx(const void* __restrict__ p, size_t i, int is64) {
    if (is64) return (int)((const long long*)p)[i];
    return ((const int*)p)[i];
}

// ---------------- CSR build ----------------
__global__ void zero_deg_mark_kernel() {
    int i = blockIdx.x * blockDim.x + threadIdx.x;
    if (i < N_NODES) {
        g_deg[i] = 0;
        g_mark[i] = 0;
    }
    if (i == 0) g_nsel = 0;
}

__global__ void degree_kernel(const void* __restrict__ edge, int E) {
    int e = blockIdx.x * blockDim.x + threadIdx.x;
    if (e >= E) return;
    int d = load_idx(edge, (size_t)E + e, g_idx64);
    atomicAdd(&g_deg[d], 1);
}

__global__ void blocksum_kernel() {
    __shared__ int ws[8];
    int i = blockIdx.x * 256 + threadIdx.x;
    int v = (i < N_NODES) ? g_deg[i] : 0;
    int lane = threadIdx.x & 31, wid = threadIdx.x >> 5;
#pragma unroll
    for (int o = 16; o; o >>= 1) v += __shfl_down_sync(0xffffffffu, v, o);
    if (lane == 0) ws[wid] = v;
    __syncthreads();
    if (threadIdx.x == 0) {
        int s = 0;
#pragma unroll
        for (int k = 0; k < 8; k++) s += ws[k];
        g_bsum[blockIdx.x] = s;
    }
}

__global__ __launch_bounds__(512) void scan_bsum_kernel(int E) {
    __shared__ int wsum[16];
    int tid = threadIdx.x, lane = tid & 31, wid = tid >> 5;
    int v = (tid < NBLK_SCAN) ? g_bsum[tid] : 0;
    int s = v;
#pragma unroll
    for (int o = 1; o < 32; o <<= 1) {
        int t = __shfl_up_sync(0xffffffffu, s, o);
        if (lane >= o) s += t;
    }
    if (lane == 31) wsum[wid] = s;
    __syncthreads();
    if (wid == 0 && lane < 16) {
        int ws = wsum[lane];
        int ss = ws;
#pragma unroll
        for (int o = 1; o < 16; o <<= 1) {
            int t = __shfl_up_sync(0xffffu, ss, o);
            if (lane >= o) ss += t;
        }
        wsum[lane] = ss;
    }
    __syncthreads();
    int excl = s - v + (wid ? wsum[wid - 1] : 0);
    if (tid < NBLK_SCAN) g_bsum[tid] = excl;
    if (tid == 0) g_rowstart[N_NODES] = E;
}

__global__ void distribute_kernel() {
    __shared__ int wsum[8];
    int tid = threadIdx.x, lane = tid & 31, wid = tid >> 5;
    int i = blockIdx.x * 256 + tid;
    int v = (i < N_NODES) ? g_deg[i] : 0;
    int s = v;
#pragma unroll
    for (int o = 1; o < 32; o <<= 1) {
        int t = __shfl_up_sync(0xffffffffu, s, o);
        if (lane >= o) s += t;
    }
    if (lane == 31) wsum[wid] = s;
    __syncthreads();
    if (wid == 0 && lane < 8) {
        int ws = wsum[lane];
        int ss = ws;
#pragma unroll
        for (int o = 1; o < 8; o <<= 1) {
            int t = __shfl_up_sync(0xffu, ss, o);
            if (lane >= o) ss += t;
        }
        wsum[lane] = ss;
    }
    __syncthreads();
    int excl = s - v + (wid ? wsum[wid - 1] : 0) + g_bsum[blockIdx.x];
    if (i < N_NODES) {
        g_rowstart[i] = excl;
        g_wptr[i] = excl;
    }
}

__global__ void fill_kernel(const void* __restrict__ edge, int E) {
    int e = blockIdx.x * blockDim.x + threadIdx.x;
    if (e >= E) return;
    int is64 = g_idx64;
    int s = load_idx(edge, e, is64);
    int d = load_idx(edge, (size_t)E + e, is64);
    int pos = atomicAdd(&g_wptr[d], 1);
    g_csr[pos] = s;
}

// ---------------- batch node selection ----------------
__global__ void mark_kernel(const void* __restrict__ idx, int B) {
    int r = blockIdx.x * blockDim.x + threadIdx.x;
    if (r >= B) return;
    int node = load_idx(idx, r, g_idx64);
    g_mark[node] = 1;
}

__global__ void compact_kernel() {
    int i = blockIdx.x * blockDim.x + threadIdx.x;
    if (i >= N_NODES) return;
    if (g_mark[i]) {
        int slot = atomicAdd(&g_nsel, 1);
        g_sel[slot] = i;
        g_node2slot[i] = slot;
    }
}

// ---------------- splits ----------------
__global__ void split_x_kernel(const float* __restrict__ x) {
    size_t i = (size_t)blockIdx.x * blockDim.x + threadIdx.x;
    const size_t n4 = (size_t)N_NODES * F_IN / 4;
    if (i >= n4) return;
    float4 v = reinterpret_cast<const float4*>(x)[i];
    split_store4(v, g_xh + i * 4, g_xl + i * 4);
}

__global__ void split_w_kernel(const float* __restrict__ W,
                               __nv_bfloat16* __restrict__ Th,
                               __nv_bfloat16* __restrict__ Tl, int K) {
    int idx = blockIdx.x * blockDim.x + threadIdx.x;
    if (idx >= K * 256) return;
    int k = idx >> 8;
    int n = idx & 255;
    __nv_bfloat16 h, l;
    split1(W[idx], h, l);
    Th[n * K + k] = h;
    Tl[n * K + k] = l;
}

// split h1 at selected slots: h1c[slot] = split(h1[sel[slot]])
__global__ void split_h1c_kernel() {
    int i = blockIdx.x * blockDim.x + threadIdx.x;   // over B_MAX * 64 float4s
    int slot = i >> 6;
    if (slot >= g_nsel) return;
    int node = g_sel[slot];
    int c4 = i & 63;
    float4 v = reinterpret_cast<const float4*>(g_h1 + (size_t)node * HID)[c4];
    size_t off = (size_t)slot * HID + c4 * 4;
    split_store4(v, g_h1ch + off, g_h1cl + off);
}

// ---------------- layer-1 aggregate -> bf16 hi/lo (all nodes) ----------------
__global__ __launch_bounds__(256) void agg1_kernel(const float* __restrict__ x) {
    int n = (int)(((size_t)blockIdx.x * blockDim.x + threadIdx.x) >> 5);
    if (n >= N_NODES) return;
    int lane = threadIdx.x & 31;
    int start = g_rowstart[n];
    int end = g_rowstart[n + 1];
    float4 acc0 = make_float4(0.f, 0.f, 0.f, 0.f);
    float4 acc1 = make_float4(0.f, 0.f, 0.f, 0.f);
    int e = start;
    for (; e + 1 < end; e += 2) {
        int s0 = g_csr[e];
        int s1 = g_csr[e + 1];
        float4 v0 = reinterpret_cast<const float4*>(x + (size_t)s0 * F_IN)[lane];
        float4 v1 = reinterpret_cast<const float4*>(x + (size_t)s1 * F_IN)[lane];
        acc0.x += v0.x; acc0.y += v0.y; acc0.z += v0.z; acc0.w += v0.w;
        acc1.x += v1.x; acc1.y += v1.y; acc1.z += v1.z; acc1.w += v1.w;
    }
    if (e < end) {
        int s0 = g_csr[e];
        float4 v0 = reinterpret_cast<const float4*>(x + (size_t)s0 * F_IN)[lane];
        acc0.x += v0.x; acc0.y += v0.y; acc0.z += v0.z; acc0.w += v0.w;
    }
    float r = 1.0f / fmaxf((float)(end - start), 1.0f);
    float4 o;
    o.x = (acc0.x + acc1.x) * r;
    o.y = (acc0.y + acc1.y) * r;
    o.z = (acc0.z + acc1.z) * r;
    o.w = (acc0.w + acc1.w) * r;
    size_t off = (size_t)n * F_IN + lane * 4;
    split_store4(o, g_a1h + off, g_a1l + off);
}

// ---------------- layer-2 aggregate (selected slots only) -> bf16 hi/lo ----------------
__global__ __launch_bounds__(256) void agg2c_kernel() {
    int slot = (int)(((size_t)blockIdx.x * blockDim.x + threadIdx.x) >> 5);
    if (slot >= g_nsel) return;
    int n = g_sel[slot];
    int lane = threadIdx.x & 31;
    int start = g_rowstart[n];
    int end = g_rowstart[n + 1];
    float4 a0 = make_float4(0.f, 0.f, 0.f, 0.f);
    float4 a1 = make_float4(0.f, 0.f, 0.f, 0.f);
    for (int e = start; e < end; e++) {
        int s = g_csr[e];
        const float4* hp = reinterpret_cast<const float4*>(g_h1 + (size_t)s * HID);
        float4 v0 = hp[lane];
        float4 v1 = hp[lane + 32];
        a0.x += v0.x; a0.y += v0.y; a0.z += v0.z; a0.w += v0.w;
        a1.x += v1.x; a1.y += v1.y; a1.z += v1.z; a1.w += v1.w;
    }
    float r = 1.0f / fmaxf((float)(end - start), 1.0f);
    a0.x *= r; a0.y *= r; a0.z *= r; a0.w *= r;
    a1.x *= r; a1.y *= r; a1.z *= r; a1.w *= r;
    size_t off = (size_t)slot * HID;
    split_store4(a0, g_a2h + off + lane * 4, g_a2l + off + lane * 4);
    split_store4(a1, g_a2h + off + 128 + lane * 4, g_a2l + off + 128 + lane * 4);
}

// ---------------- bf16x2 tensor-core dual GEMM (pre-split operands) ----------------
__device__ __forceinline__ void mma_bf16(float* c, const uint32_t* a, const uint32_t* b) {
    asm volatile(
        "mma.sync.aligned.m16n8k16.row.col.f32.bf16.bf16.f32 "
        "{%0,%1,%2,%3}, {%4,%5,%6,%7}, {%8,%9}, {%0,%1,%2,%3};"
        : "+f"(c[0]), "+f"(c[1]), "+f"(c[2]), "+f"(c[3])
        : "r"(a[0]), "r"(a[1]), "r"(a[2]), "r"(a[3]), "r"(b[0]), "r"(b[1]));
}

__device__ __forceinline__ void st_smem32(__nv_bfloat16* dst, const uint4* r) {
    float2* d = reinterpret_cast<float2*>(dst);
    d[0] = make_float2(__uint_as_float(r[0].x), __uint_as_float(r[0].y));
    d[1] = make_float2(__uint_as_float(r[0].z), __uint_as_float(r[0].w));
    d[2] = make_float2(__uint_as_float(r[1].x), __uint_as_float(r[1].y));
    d[3] = make_float2(__uint_as_float(r[1].z), __uint_as_float(r[1].w));
}

// C[M,256] = relu( A0@B0^T + A1@B1^T + bias ); A*,B* pre-split bf16 hi/lo. B is [256][K].
__global__ __launch_bounds__(256) void gemm_dual_pre_kernel(
    const __nv_bfloat16* __restrict__ A0h, const __nv_bfloat16* __restrict__ A0l, int K0,
    const __nv_bfloat16* __restrict__ A1h, const __nv_bfloat16* __restrict__ A1l, int K1,
    const __nv_bfloat16* __restrict__ B0h, const __nv_bfloat16* __restrict__ B0l,
    const __nv_bfloat16* __restrict__ B1h, const __nv_bfloat16* __restrict__ B1l,
    const float* __restrict__ bias, float* __restrict__ C, int M) {
    const int N = 256;
    const int SP = 40;
    __shared__ __nv_bfloat16 Ah[128][SP];
    __shared__ __nv_bfloat16 Al[128][SP];
    __shared__ __nv_bfloat16 Bh[128][SP];
    __shared__ __nv_bfloat16 Bl[128][SP];

    int tid = threadIdx.x;
    int lane = tid & 31;
    int wid = tid >> 5;
    int bm = blockIdx.x * 128;
    int bn = blockIdx.y * 128;
    int wm = (wid >> 2) * 64;
    int wn = (wid & 3) * 32;

    float acc[4][4][4];
#pragma unroll
    for (int mi = 0; mi < 4; mi++)
#pragma unroll
        for (int ni = 0; ni < 4; ni++)
#pragma unroll
            for (int q = 0; q < 4; q++) acc[mi][ni][q] = 0.f;

    int arow = tid >> 1;
    int ak0 = (tid & 1) * 16;
    int brow = tid >> 1;
    int bk0 = (tid & 1) * 16;

    int g = lane >> 2;
    int tq = (lane & 3) * 2;

    int K = K0 + K1;
    uint4 rah[2], ral[2], rbh[2], rbl[2];

    auto gload = [&](int kt) {
        const __nv_bfloat16 *pah, *pal, *pbh, *pbl;
        int lda, kloc;
        if (kt < K0) { pah = A0h; pal = A0l; pbh = B0h; pbl = B0l; lda = K0; kloc = kt; }
        else         { pah = A1h; pal = A1l; pbh = B1h; pbl = B1l; lda = K1; kloc = kt - K0; }
        int gr = bm + arow;
        if (gr < M) {
            const uint4* p = reinterpret_cast<const uint4*>(pah + (size_t)gr * lda + kloc + ak0);
            rah[0] = p[0]; rah[1] = p[1];
            const uint4* q = reinterpret_cast<const uint4*>(pal + (size_t)gr * lda + kloc + ak0);
            ral[0] = q[0]; ral[1] = q[1];
        } else {
            rah[0] = rah[1] = ral[0] = ral[1] = make_uint4(0, 0, 0, 0);
        }
        const uint4* pb = reinterpret_cast<const uint4*>(pbh + (size_t)(bn + brow) * lda + kloc + bk0);
        rbh[0] = pb[0]; rbh[1] = pb[1];
        const uint4* qb = reinterpret_cast<const uint4*>(pbl + (size_t)(bn + brow) * lda + kloc + bk0);
        rbl[0] = qb[0]; rbl[1] = qb[1];
    };
    auto sstore = [&]() {
        st_smem32(&Ah[arow][ak0], rah);
        st_smem32(&Al[arow][ak0], ral);
        st_smem32(&Bh[brow][bk0], rbh);
        st_smem32(&Bl[brow][bk0], rbl);
    };

    gload(0);
    sstore();
    __syncthreads();

    for (int kt = 0; kt < K; kt += 32) {
        bool more = (kt + 32) < K;
        if (more) gload(kt + 32);

#pragma unroll
        for (int ks = 0; ks < 2; ks++) {
            int k0 = ks * 16;
            uint32_t afh[4][4], afl[4][4], bfh[4][2], bfl[4][2];
#pragma unroll
            for (int mi = 0; mi < 4; mi++) {
                int r0 = wm + mi * 16 + g;
                afh[mi][0] = *reinterpret_cast<const uint32_t*>(&Ah[r0][k0 + tq]);
                afh[mi][1] = *reinterpret_cast<const uint32_t*>(&Ah[r0 + 8][k0 + tq]);
                afh[mi][2] = *reinterpret_cast<const uint32_t*>(&Ah[r0][k0 + tq + 8]);
                afh[mi][3] = *reinterpret_cast<const uint32_t*>(&Ah[r0 + 8][k0 + tq + 8]);
                afl[mi][0] = *reinterpret_cast<const uint32_t*>(&Al[r0][k0 + tq]);
                afl[mi][1] = *reinterpret_cast<const uint32_t*>(&Al[r0 + 8][k0 + tq]);
                afl[mi][2] = *reinterpret_cast<const uint32_t*>(&Al[r0][k0 + tq + 8]);
                afl[mi][3] = *reinterpret_cast<const uint32_t*>(&Al[r0 + 8][k0 + tq + 8]);
            }
#pragma unroll
            for (int ni = 0; ni < 4; ni++) {
                int nn = wn + ni * 8 + g;
                bfh[ni][0] = *reinterpret_cast<const uint32_t*>(&Bh[nn][k0 + tq]);
                bfh[ni][1] = *reinterpret_cast<const uint32_t*>(&Bh[nn][k0 + tq + 8]);
                bfl[ni][0] = *reinterpret_cast<const uint32_t*>(&Bl[nn][k0 + tq]);
                bfl[ni][1] = *reinterpret_cast<const uint32_t*>(&Bl[nn][k0 + tq + 8]);
            }
#pragma unroll
            for (int mi = 0; mi < 4; mi++)
#pragma unroll
                for (int ni = 0; ni < 4; ni++) {
                    mma_bf16(acc[mi][ni], afh[mi], bfh[ni]);
                    mma_bf16(acc[mi][ni], afh[mi], bfl[ni]);
                    mma_bf16(acc[mi][ni], afl[mi], bfh[ni]);
                }
        }
        if (more) {
            __syncthreads();
            sstore();
            __syncthreads();
        }
    }

#pragma unroll
    for (int mi = 0; mi < 4; mi++) {
#pragma unroll
        for (int ni = 0; ni < 4; ni++) {
            int col = bn + wn + ni * 8 + tq;
            float bv0 = bias[col];
            float bv1 = bias[col + 1];
#pragma unroll
            for (int h = 0; h < 2; h++) {
                int r = bm + wm + mi * 16 + g + h * 8;
                if (r < M) {
                    float v0 = fmaxf(acc[mi][ni][h * 2 + 0] + bv0, 0.f);
                    float v1 = fmaxf(acc[mi][ni][h * 2 + 1] + bv1, 0.f);
                    *reinterpret_cast<float2*>(&C[(size_t)r * N + col]) = make_float2(v0, v1);
                }
            }
        }
    }
}

// ---------------- MLP head (reads compacted h2c via node->slot) ----------------
__global__ __launch_bounds__(256) void mlp_kernel(
    const float* __restrict__ x_tab, const void* __restrict__ idx,
    const float* __restrict__ W1, const float* __restrict__ b1,
    const float* __restrict__ W2, const float* __restrict__ b2,
    const float* __restrict__ W3, const float* __restrict__ b3,
    float* __restrict__ out, int B) {
    __shared__ float zs[8][280];
    __shared__ float z1s[8][64];
    int w = threadIdx.x >> 5;
    int lane = threadIdx.x & 31;
    int row = blockIdx.x * 8 + w;
    if (row >= B) return;
    int node = load_idx(idx, row, g_idx64);
    int slot = g_node2slot[node];
    const float4* h = reinterpret_cast<const float4*>(g_h2c + (size_t)slot * HID);
    float4 v = h[lane];
    *reinterpret_cast<float4*>(&zs[w][lane * 4]) = v;
    v = h[lane + 32];
    *reinterpret_cast<float4*>(&zs[w][128 + lane * 4]) = v;
    if (lane < 16) zs[w][256 + lane] = x_tab[row * 16 + lane];
    __syncwarp();

    float a0 = b1[lane];
    float a1 = b1[lane + 32];
#pragma unroll 4
    for (int k = 0; k < 272; k++) {
        float zk = zs[w][k];
        a0 += zk * W1[k * 64 + lane];
        a1 += zk * W1[k * 64 + lane + 32];
    }
    z1s[w][lane] = fmaxf(a0, 0.f);
    z1s[w][lane + 32] = fmaxf(a1, 0.f);
    __syncwarp();

    float a = b2[lane];
#pragma unroll
    for (int k = 0; k < 64; k++) a += z1s[w][k] * W2[k * 32 + lane];
    float z2 = fmaxf(a, 0.f);

    float p = z2 * W3[lane];
#pragma unroll
    for (int off = 16; off; off >>= 1) p += __shfl_down_sync(0xffffffffu, p, off);
    if (lane == 0) out[row] = p + b3[0];
}

// ---------------- launch ----------------
extern "C" void kernel_launch(void* const* d_in, const int* in_sizes, int n_in,
                              void* d_out, int out_size) {
    const float* x     = (const float*)d_in[0];
    const void* edge   = d_in[1];
    const void* idxb   = d_in[2];
    const float* x_tab = (const float*)d_in[3];
    const float* Wl1 = (const float*)d_in[4];
    const float* bl1 = (const float*)d_in[5];
    const float* Wr1 = (const float*)d_in[6];
    const float* Wl2 = (const float*)d_in[7];
    const float* bl2 = (const float*)d_in[8];
    const float* Wr2 = (const float*)d_in[9];
    const float* W1  = (const float*)d_in[10];
    const float* b1  = (const float*)d_in[11];
    const float* W2  = (const float*)d_in[12];
    const float* b2  = (const float*)d_in[13];
    const float* W3  = (const float*)d_in[14];
    const float* b3  = (const float*)d_in[15];
    float* out = (float*)d_out;

    int E = in_sizes[1] / 2;
    if (E > E_MAX) E = E_MAX;
    int B = in_sizes[2];
    if (B > B_MAX) B = B_MAX;

    __nv_bfloat16 *p_xh, *p_xl, *p_a1h, *p_a1l, *p_h1ch, *p_h1cl, *p_a2h, *p_a2l;
    __nv_bfloat16 *p_wl1h, *p_wl1l, *p_wr1h, *p_wr1l, *p_wl2h, *p_wl2l, *p_wr2h, *p_wr2l;
    float *p_h1, *p_h2c;
    cudaGetSymbolAddress((void**)&p_xh, g_xh);
    cudaGetSymbolAddress((void**)&p_xl, g_xl);
    cudaGetSymbolAddress((void**)&p_a1h, g_a1h);
    cudaGetSymbolAddress((void**)&p_a1l, g_a1l);
    cudaGetSymbolAddress((void**)&p_h1, g_h1);
    cudaGetSymbolAddress((void**)&p_h1ch, g_h1ch);
    cudaGetSymbolAddress((void**)&p_h1cl, g_h1cl);
    cudaGetSymbolAddress((void**)&p_a2h, g_a2h);
    cudaGetSymbolAddress((void**)&p_a2l, g_a2l);
    cudaGetSymbolAddress((void**)&p_h2c, g_h2c);
    cudaGetSymbolAddress((void**)&p_wl1h, g_wl1h);
    cudaGetSymbolAddress((void**)&p_wl1l, g_wl1l);
    cudaGetSymbolAddress((void**)&p_wr1h, g_wr1h);
    cudaGetSymbolAddress((void**)&p_wr1l, g_wr1l);
    cudaGetSymbolAddress((void**)&p_wl2h, g_wl2h);
    cudaGetSymbolAddress((void**)&p_wl2l, g_wl2l);
    cudaGetSymbolAddress((void**)&p_wr2h, g_wr2h);
    cudaGetSymbolAddress((void**)&p_wr2l, g_wr2l);

    // 0. sniff dtype
    sniff_kernel<<<1, 32>>>((const int*)edge);

    // 1. CSR build + selection reset
    zero_deg_mark_kernel<<<NBLK_SCAN, 256>>>();
    degree_kernel<<<(E + 255) / 256, 256>>>(edge, E);
    blocksum_kernel<<<NBLK_SCAN, 256>>>();
    scan_bsum_kernel<<<1, 512>>>(E);
    distribute_kernel<<<NBLK_SCAN, 256>>>();
    fill_kernel<<<(E + 255) / 256, 256>>>(edge, E);

    // 2. batch-node selection
    mark_kernel<<<(B + 255) / 256, 256>>>(idxb, B);
    compact_kernel<<<NBLK_SCAN, 256>>>();

    // 3. pre-split x and weights
    {
        size_t n4 = (size_t)N_NODES * F_IN / 4;
        split_x_kernel<<<(int)((n4 + 255) / 256), 256>>>(x);
        split_w_kernel<<<(F_IN * 256 + 255) / 256, 256>>>(Wl1, p_wl1h, p_wl1l, F_IN);
        split_w_kernel<<<(F_IN * 256 + 255) / 256, 256>>>(Wr1, p_wr1h, p_wr1l, F_IN);
        split_w_kernel<<<(HID * 256 + 255) / 256, 256>>>(Wl2, p_wl2h, p_wl2l, HID);
        split_w_kernel<<<(HID * 256 + 255) / 256, 256>>>(Wr2, p_wr2h, p_wr2l, HID);
    }

    // 4. layer-1 mean aggregate (all nodes)
    agg1_kernel<<<(N_NODES * 32 + 255) / 256, 256>>>(x);

    // 5. h1 = relu(mean1 @ Wl1 + x @ Wr1 + bl1)  (all nodes)
    {
        dim3 grid((N_NODES + 127) / 128, 2);
        gemm_dual_pre_kernel<<<grid, 256>>>(
            p_a1h, p_a1l, F_IN, p_xh, p_xl, F_IN,
            p_wl1h, p_wl1l, p_wr1h, p_wr1l,
            bl1, p_h1, N_NODES);
    }

    // 6. selected-node layer-2 inputs: agg2 + h1 split (compacted)
    agg2c_kernel<<<(B * 32 + 255) / 256, 256>>>();
    split_h1c_kernel<<<(B * 64 + 255) / 256, 256>>>();

    // 7. h2c = relu(agg2c @ Wl2 + h1c @ Wr2 + bl2)  (selected slots, padded to B)
    {
        dim3 grid((B + 127) / 128, 2);
        gemm_dual_pre_kernel<<<grid, 256>>>(
            p_a2h, p_a2l, HID, p_h1ch, p_h1cl, HID,
            p_wl2h, p_wl2l, p_wr2h, p_wr2l,
            bl2, p_h2c, B);
    }

    // 8. MLP head
    mlp_kernel<<<(B + 7) / 8, 256>>>(x_tab, idxb, W1, b1, W2, b2, W3, b3, out, B);
}

// round 8
// speedup vs baseline: 6.0810x; 1.1232x over previous
#include <cuda_runtime.h>
#include <cuda_bf16.h>
#include <cstdint>
#include <cstddef>

#define N_NODES 100000
#define F_IN 128
#define HID 256
#define E_MAX 1600000
#define B_MAX 16384
#define NBLK_SCAN ((N_NODES + 255) / 256)

// ---------------- scratch (device globals; no allocation allowed) ----------------
__device__ int g_idx64;
__device__ int g_deg[N_NODES];
__device__ int g_bsum[NBLK_SCAN + 1];
__device__ int g_rowstart[N_NODES + 1];
__device__ int g_wptr[N_NODES];
__device__ int g_csr[E_MAX];

__device__ int g_mark[N_NODES];
__device__ int g_node2slot[N_NODES];
__device__ int g_sel[B_MAX];
__device__ int g_nsel;

__device__ __nv_bfloat16 g_xh[(size_t)N_NODES * F_IN];
__device__ __nv_bfloat16 g_xl[(size_t)N_NODES * F_IN];
__device__ __nv_bfloat16 g_a1h[(size_t)N_NODES * F_IN];
__device__ __nv_bfloat16 g_a1l[(size_t)N_NODES * F_IN];
__device__ float         g_h1[(size_t)N_NODES * HID];
__device__ __nv_bfloat16 g_h1ch[(size_t)B_MAX * HID];
__device__ __nv_bfloat16 g_h1cl[(size_t)B_MAX * HID];
__device__ __nv_bfloat16 g_a2h[(size_t)B_MAX * HID];
__device__ __nv_bfloat16 g_a2l[(size_t)B_MAX * HID];
__device__ float         g_h2c[(size_t)B_MAX * HID];

__device__ __nv_bfloat16 g_wl1h[256 * F_IN], g_wl1l[256 * F_IN];
__device__ __nv_bfloat16 g_wr1h[256 * F_IN], g_wr1l[256 * F_IN];
__device__ __nv_bfloat16 g_wl2h[256 * HID], g_wl2l[256 * HID];
__device__ __nv_bfloat16 g_wr2h[256 * HID], g_wr2l[256 * HID];

// ---------------- helpers ----------------
__device__ __forceinline__ void split1(float v, __nv_bfloat16& h, __nv_bfloat16& l) {
    h = __float2bfloat16(v);
    l = __float2bfloat16(v - __bfloat162float(h));
}

__device__ __forceinline__ void split_store4(float4 v, __nv_bfloat16* ph, __nv_bfloat16* pl) {
    __nv_bfloat16 h0, h1, h2, h3, l0, l1, l2, l3;
    split1(v.x, h0, l0); split1(v.y, h1, l1);
    split1(v.z, h2, l2); split1(v.w, h3, l3);
    __nv_bfloat162* H = reinterpret_cast<__nv_bfloat162*>(ph);
    __nv_bfloat162* L = reinterpret_cast<__nv_bfloat162*>(pl);
    H[0] = __halves2bfloat162(h0, h1);
    H[1] = __halves2bfloat162(h2, h3);
    L[0] = __halves2bfloat162(l0, l1);
    L[1] = __halves2bfloat162(l2, l3);
}

__device__ __forceinline__ uint32_t smem_to_u32(const void* smem_ptr) {
    uint32_t addr;
    asm("{ .reg .u64 tmp; cvta.to.shared.u64 tmp, %1; cvt.u32.u64 %0, tmp; }"
        : "=r"(addr) : "l"(smem_ptr));
    return addr;
}

__device__ __forceinline__ void ldsm_x4(uint32_t* r, uint32_t a) {
    asm volatile("ldmatrix.sync.aligned.m8n8.x4.shared.b16 {%0,%1,%2,%3}, [%4];"
                 : "=r"(r[0]), "=r"(r[1]), "=r"(r[2]), "=r"(r[3]) : "r"(a));
}
__device__ __forceinline__ void ldsm_x2(uint32_t* r, uint32_t a) {
    asm volatile("ldmatrix.sync.aligned.m8n8.x2.shared.b16 {%0,%1}, [%2];"
                 : "=r"(r[0]), "=r"(r[1]) : "r"(a));
}

// ---------------- index dtype sniff ----------------
__global__ void sniff_kernel(const int* __restrict__ e) {
    if (threadIdx.x == 0 && blockIdx.x == 0) {
        int allz = 1;
        for (int i = 0; i < 64; i++)
            if (e[2 * i + 1] != 0) { allz = 0; break; }
        g_idx64 = allz;
    }
}

__device__ __forceinline__ int load_idx(const void* __restrict__ p, size_t i, int is64) {
    if (is64) return (int)((const long long*)p)[i];
    return ((const int*)p)[i];
}

// ---------------- CSR build ----------------
__global__ void zero_deg_mark_kernel() {
    int i = blockIdx.x * blockDim.x + threadIdx.x;
    if (i < N_NODES) {
        g_deg[i] = 0;
        g_mark[i] = 0;
    }
    if (i == 0) g_nsel = 0;
}

__global__ void degree_kernel(const void* __restrict__ edge, int E) {
    int e = blockIdx.x * blockDim.x + threadIdx.x;
    if (e >= E) return;
    int d = load_idx(edge, (size_t)E + e, g_idx64);
    atomicAdd(&g_deg[d], 1);
}

__global__ void blocksum_kernel() {
    __shared__ int ws[8];
    int i = blockIdx.x * 256 + threadIdx.x;
    int v = (i < N_NODES) ? g_deg[i] : 0;
    int lane = threadIdx.x & 31, wid = threadIdx.x >> 5;
#pragma unroll
    for (int o = 16; o; o >>= 1) v += __shfl_down_sync(0xffffffffu, v, o);
    if (lane == 0) ws[wid] = v;
    __syncthreads();
    if (threadIdx.x == 0) {
        int s = 0;
#pragma unroll
        for (int k = 0; k < 8; k++) s += ws[k];
        g_bsum[blockIdx.x] = s;
    }
}

__global__ __launch_bounds__(512) void scan_bsum_kernel(int E) {
    __shared__ int wsum[16];
    int tid = threadIdx.x, lane = tid & 31, wid = tid >> 5;
    int v = (tid < NBLK_SCAN) ? g_bsum[tid] : 0;
    int s = v;
#pragma unroll
    for (int o = 1; o < 32; o <<= 1) {
        int t = __shfl_up_sync(0xffffffffu, s, o);
        if (lane >= o) s += t;
    }
    if (lane == 31) wsum[wid] = s;
    __syncthreads();
    if (wid == 0 && lane < 16) {
        int ws = wsum[lane];
        int ss = ws;
#pragma unroll
        for (int o = 1; o < 16; o <<= 1) {
            int t = __shfl_up_sync(0xffffu, ss, o);
            if (lane >= o) ss += t;
        }
        wsum[lane] = ss;
    }
    __syncthreads();
    int excl = s - v + (wid ? wsum[wid - 1] : 0);
    if (tid < NBLK_SCAN) g_bsum[tid] = excl;
    if (tid == 0) g_rowstart[N_NODES] = E;
}

__global__ void distribute_kernel() {
    __shared__ int wsum[8];
    int tid = threadIdx.x, lane = tid & 31, wid = tid >> 5;
    int i = blockIdx.x * 256 + tid;
    int v = (i < N_NODES) ? g_deg[i] : 0;
    int s = v;
#pragma unroll
    for (int o = 1; o < 32; o <<= 1) {
        int t = __shfl_up_sync(0xffffffffu, s, o);
        if (lane >= o) s += t;
    }
    if (lane == 31) wsum[wid] = s;
    __syncthreads();
    if (wid == 0 && lane < 8) {
        int ws = wsum[lane];
        int ss = ws;
#pragma unroll
        for (int o = 1; o < 8; o <<= 1) {
            int t = __shfl_up_sync(0xffu, ss, o);
            if (lane >= o) ss += t;
        }
        wsum[lane] = ss;
    }
    __syncthreads();
    int excl = s - v + (wid ? wsum[wid - 1] : 0) + g_bsum[blockIdx.x];
    if (i < N_NODES) {
        g_rowstart[i] = excl;
        g_wptr[i] = excl;
    }
}

__global__ void fill_kernel(const void* __restrict__ edge, int E) {
    int e = blockIdx.x * blockDim.x + threadIdx.x;
    if (e >= E) return;
    int is64 = g_idx64;
    int s = load_idx(edge, e, is64);
    int d = load_idx(edge, (size_t)E + e, is64);
    int pos = atomicAdd(&g_wptr[d], 1);
    g_csr[pos] = s;
}

// ---------------- batch node selection ----------------
__global__ void mark_kernel(const void* __restrict__ idx, int B) {
    int r = blockIdx.x * blockDim.x + threadIdx.x;
    if (r >= B) return;
    int node = load_idx(idx, r, g_idx64);
    g_mark[node] = 1;
}

__global__ void compact_kernel() {
    int i = blockIdx.x * blockDim.x + threadIdx.x;
    if (i >= N_NODES) return;
    if (g_mark[i]) {
        int slot = atomicAdd(&g_nsel, 1);
        g_sel[slot] = i;
        g_node2slot[i] = slot;
    }
}

// ---------------- splits ----------------
__global__ void split_x_kernel(const float* __restrict__ x) {
    size_t i = (size_t)blockIdx.x * blockDim.x + threadIdx.x;
    const size_t n4 = (size_t)N_NODES * F_IN / 4;
    if (i >= n4) return;
    float4 v = reinterpret_cast<const float4*>(x)[i];
    split_store4(v, g_xh + i * 4, g_xl + i * 4);
}

__global__ void split_w_kernel(const float* __restrict__ W,
                               __nv_bfloat16* __restrict__ Th,
                               __nv_bfloat16* __restrict__ Tl, int K) {
    int idx = blockIdx.x * blockDim.x + threadIdx.x;
    if (idx >= K * 256) return;
    int k = idx >> 8;
    int n = idx & 255;
    __nv_bfloat16 h, l;
    split1(W[idx], h, l);
    Th[n * K + k] = h;
    Tl[n * K + k] = l;
}

__global__ void split_h1c_kernel() {
    int i = blockIdx.x * blockDim.x + threadIdx.x;
    int slot = i >> 6;
    if (slot >= g_nsel) return;
    int node = g_sel[slot];
    int c4 = i & 63;
    float4 v = reinterpret_cast<const float4*>(g_h1 + (size_t)node * HID)[c4];
    size_t off = (size_t)slot * HID + c4 * 4;
    split_store4(v, g_h1ch + off, g_h1cl + off);
}

// ---------------- layer-1 aggregate -> bf16 hi/lo ----------------
__global__ __launch_bounds__(256) void agg1_kernel(const float* __restrict__ x) {
    int n = (int)(((size_t)blockIdx.x * blockDim.x + threadIdx.x) >> 5);
    if (n >= N_NODES) return;
    int lane = threadIdx.x & 31;
    int start = g_rowstart[n];
    int end = g_rowstart[n + 1];
    float4 acc0 = make_float4(0.f, 0.f, 0.f, 0.f);
    float4 acc1 = make_float4(0.f, 0.f, 0.f, 0.f);
    int e = start;
    for (; e + 1 < end; e += 2) {
        int s0 = g_csr[e];
        int s1 = g_csr[e + 1];
        float4 v0 = reinterpret_cast<const float4*>(x + (size_t)s0 * F_IN)[lane];
        float4 v1 = reinterpret_cast<const float4*>(x + (size_t)s1 * F_IN)[lane];
        acc0.x += v0.x; acc0.y += v0.y; acc0.z += v0.z; acc0.w += v0.w;
        acc1.x += v1.x; acc1.y += v1.y; acc1.z += v1.z; acc1.w += v1.w;
    }
    if (e < end) {
        int s0 = g_csr[e];
        float4 v0 = reinterpret_cast<const float4*>(x + (size_t)s0 * F_IN)[lane];
        acc0.x += v0.x; acc0.y += v0.y; acc0.z += v0.z; acc0.w += v0.w;
    }
    float r = 1.0f / fmaxf((float)(end - start), 1.0f);
    float4 o;
    o.x = (acc0.x + acc1.x) * r;
    o.y = (acc0.y + acc1.y) * r;
    o.z = (acc0.z + acc1.z) * r;
    o.w = (acc0.w + acc1.w) * r;
    size_t off = (size_t)n * F_IN + lane * 4;
    split_store4(o, g_a1h + off, g_a1l + off);
}

// ---------------- layer-2 aggregate (selected slots) -> bf16 hi/lo ----------------
__global__ __launch_bounds__(256) void agg2c_kernel() {
    int slot = (int)(((size_t)blockIdx.x * blockDim.x + threadIdx.x) >> 5);
    if (slot >= g_nsel) return;
    int n = g_sel[slot];
    int lane = threadIdx.x & 31;
    int start = g_rowstart[n];
    int end = g_rowstart[n + 1];
    float4 a0 = make_float4(0.f, 0.f, 0.f, 0.f);
    float4 a1 = make_float4(0.f, 0.f, 0.f, 0.f);
    for (int e = start; e < end; e++) {
        int s = g_csr[e];
        const float4* hp = reinterpret_cast<const float4*>(g_h1 + (size_t)s * HID);
        float4 v0 = hp[lane];
        float4 v1 = hp[lane + 32];
        a0.x += v0.x; a0.y += v0.y; a0.z += v0.z; a0.w += v0.w;
        a1.x += v1.x; a1.y += v1.y; a1.z += v1.z; a1.w += v1.w;
    }
    float r = 1.0f / fmaxf((float)(end - start), 1.0f);
    a0.x *= r; a0.y *= r; a0.z *= r; a0.w *= r;
    a1.x *= r; a1.y *= r; a1.z *= r; a1.w *= r;
    size_t off = (size_t)slot * HID;
    split_store4(a0, g_a2h + off + lane * 4, g_a2l + off + lane * 4);
    split_store4(a1, g_a2h + off + 128 + lane * 4, g_a2l + off + 128 + lane * 4);
}

// ---------------- bf16x2 tensor-core dual GEMM: double-buffered + ldmatrix ----------------
__device__ __forceinline__ void mma_bf16(float* c, const uint32_t* a, const uint32_t* b) {
    asm volatile(
        "mma.sync.aligned.m16n8k16.row.col.f32.bf16.bf16.f32 "
        "{%0,%1,%2,%3}, {%4,%5,%6,%7}, {%8,%9}, {%0,%1,%2,%3};"
        : "+f"(c[0]), "+f"(c[1]), "+f"(c[2]), "+f"(c[3])
        : "r"(a[0]), "r"(a[1]), "r"(a[2]), "r"(a[3]), "r"(b[0]), "r"(b[1]));
}

// smem layout per buffer: Ah(10240) Al(10240) Bh(10240) Bl(10240); 2 buffers
#define GROWB 80                 // 40 bf16 per row = 80 bytes
#define GAB 10240                // 128 rows * 80 B
#define GBUFB 40960
#define GEMM_SMEM 81920

__global__ __launch_bounds__(256) void gemm_dual_pre_kernel(
    const __nv_bfloat16* __restrict__ A0h, const __nv_bfloat16* __restrict__ A0l, int K0,
    const __nv_bfloat16* __restrict__ A1h, const __nv_bfloat16* __restrict__ A1l, int K1,
    const __nv_bfloat16* __restrict__ B0h, const __nv_bfloat16* __restrict__ B0l,
    const __nv_bfloat16* __restrict__ B1h, const __nv_bfloat16* __restrict__ B1l,
    const float* __restrict__ bias, float* __restrict__ C, int M) {
    const int N = 256;
    extern __shared__ char gsm[];
    uint32_t sbase = smem_to_u32(gsm);

    int tid = threadIdx.x;
    int lane = tid & 31;
    int wid = tid >> 5;
    int bm = blockIdx.x * 128;
    int bn = blockIdx.y * 128;
    int wm = (wid >> 2) * 64;
    int wn = (wid & 3) * 32;

    float acc[4][4][4];
#pragma unroll
    for (int mi = 0; mi < 4; mi++)
#pragma unroll
        for (int ni = 0; ni < 4; ni++)
#pragma unroll
            for (int q = 0; q < 4; q++) acc[mi][ni][q] = 0.f;

    int arow = tid >> 1;
    int ak0 = (tid & 1) * 16;           // elems
    int g = lane >> 2;
    int tq = (lane & 3) * 2;

    // ldmatrix lane addressing
    int lrA = lane & 15;
    int lcA = (lane >> 4) << 3;         // 0 / 8
    int lrB = lane & 7;
    int lcB = ((lane >> 3) & 1) << 3;   // 0 / 8 (lanes >=16 ignored for x2)

    int K = K0 + K1;
    uint4 rah[2], ral[2], rbh[2], rbl[2];

    auto gload = [&](int kt) {
        const __nv_bfloat16 *pah, *pal, *pbh, *pbl;
        int lda, kloc;
        if (kt < K0) { pah = A0h; pal = A0l; pbh = B0h; pbl = B0l; lda = K0; kloc = kt; }
        else         { pah = A1h; pal = A1l; pbh = B1h; pbl = B1l; lda = K1; kloc = kt - K0; }
        int gr = bm + arow;
        if (gr < M) {
            const uint4* p = reinterpret_cast<const uint4*>(pah + (size_t)gr * lda + kloc + ak0);
            rah[0] = p[0]; rah[1] = p[1];
            const uint4* q = reinterpret_cast<const uint4*>(pal + (size_t)gr * lda + kloc + ak0);
            ral[0] = q[0]; ral[1] = q[1];
        } else {
            rah[0] = rah[1] = ral[0] = ral[1] = make_uint4(0, 0, 0, 0);
        }
        const uint4* pb = reinterpret_cast<const uint4*>(pbh + (size_t)(bn + arow) * lda + kloc + ak0);
        rbh[0] = pb[0]; rbh[1] = pb[1];
        const uint4* qb = reinterpret_cast<const uint4*>(pbl + (size_t)(bn + arow) * lda + kloc + ak0);
        rbl[0] = qb[0]; rbl[1] = qb[1];
    };
    auto sstore = [&](int buf) {
        char* b = gsm + buf * GBUFB;
        char* pa = b + arow * GROWB + ak0 * 2;
        *reinterpret_cast<uint4*>(pa) = rah[0];
        *reinterpret_cast<uint4*>(pa + 16) = rah[1];
        char* pl = b + GAB + arow * GROWB + ak0 * 2;
        *reinterpret_cast<uint4*>(pl) = ral[0];
        *reinterpret_cast<uint4*>(pl + 16) = ral[1];
        char* pb2 = b + 2 * GAB + arow * GROWB + ak0 * 2;
        *reinterpret_cast<uint4*>(pb2) = rbh[0];
        *reinterpret_cast<uint4*>(pb2 + 16) = rbh[1];
        char* pl2 = b + 3 * GAB + arow * GROWB + ak0 * 2;
        *reinterpret_cast<uint4*>(pl2) = rbl[0];
        *reinterpret_cast<uint4*>(pl2 + 16) = rbl[1];
    };

    gload(0);
    sstore(0);
    __syncthreads();

    int buf = 0;
    for (int kt = 0; kt < K; kt += 32) {
        bool more = (kt + 32) < K;
        if (more) gload(kt + 32);

        uint32_t bb = sbase + buf * GBUFB;
#pragma unroll
        for (int ks = 0; ks < 2; ks++) {
            int k0 = ks * 16;
            uint32_t afh[4][4], afl[4][4], bfh[4][2], bfl[4][2];
            uint32_t aA = bb + (wm + lrA) * GROWB + (k0 + lcA) * 2;
#pragma unroll
            for (int mi = 0; mi < 4; mi++) {
                ldsm_x4(afh[mi], aA + mi * (16 * GROWB));
                ldsm_x4(afl[mi], aA + GAB + mi * (16 * GROWB));
            }
            uint32_t aB = bb + 2 * GAB + (wn + lrB) * GROWB + (k0 + lcB) * 2;
#pragma unroll
            for (int ni = 0; ni < 4; ni++) {
                ldsm_x2(bfh[ni], aB + ni * (8 * GROWB));
                ldsm_x2(bfl[ni], aB + GAB + ni * (8 * GROWB));
            }
#pragma unroll
            for (int mi = 0; mi < 4; mi++)
#pragma unroll
                for (int ni = 0; ni < 4; ni++) {
                    mma_bf16(acc[mi][ni], afh[mi], bfh[ni]);
                    mma_bf16(acc[mi][ni], afh[mi], bfl[ni]);
                    mma_bf16(acc[mi][ni], afl[mi], bfh[ni]);
                }
        }
        if (more) {
            sstore(buf ^ 1);
            __syncthreads();
            buf ^= 1;
        }
    }

#pragma unroll
    for (int mi = 0; mi < 4; mi++) {
#pragma unroll
        for (int ni = 0; ni < 4; ni++) {
            int col = bn + wn + ni * 8 + tq;
            float bv0 = bias[col];
            float bv1 = bias[col + 1];
#pragma unroll
            for (int h = 0; h < 2; h++) {
                int r = bm + wm + mi * 16 + g + h * 8;
                if (r < M) {
                    float v0 = fmaxf(acc[mi][ni][h * 2 + 0] + bv0, 0.f);
                    float v1 = fmaxf(acc[mi][ni][h * 2 + 1] + bv1, 0.f);
                    *reinterpret_cast<float2*>(&C[(size_t)r * N + col]) = make_float2(v0, v1);
                }
            }
        }
    }
}

// ---------------- MLP head ----------------
__global__ __launch_bounds__(256) void mlp_kernel(
    const float* __restrict__ x_tab, const void* __restrict__ idx,
    const float* __restrict__ W1, const float* __restrict__ b1,
    const float* __restrict__ W2, const float* __restrict__ b2,
    const float* __restrict__ W3, const float* __restrict__ b3,
    float* __restrict__ out, int B) {
    __shared__ float zs[8][280];
    __shared__ float z1s[8][64];
    int w = threadIdx.x >> 5;
    int lane = threadIdx.x & 31;
    int row = blockIdx.x * 8 + w;
    if (row >= B) return;
    int node = load_idx(idx, row, g_idx64);
    int slot = g_node2slot[node];
    const float4* h = reinterpret_cast<const float4*>(g_h2c + (size_t)slot * HID);
    float4 v = h[lane];
    *reinterpret_cast<float4*>(&zs[w][lane * 4]) = v;
    v = h[lane + 32];
    *reinterpret_cast<float4*>(&zs[w][128 + lane * 4]) = v;
    if (lane < 16) zs[w][256 + lane] = x_tab[row * 16 + lane];
    __syncwarp();

    float a0 = b1[lane];
    float a1 = b1[lane + 32];
#pragma unroll 4
    for (int k = 0; k < 272; k++) {
        float zk = zs[w][k];
        a0 += zk * W1[k * 64 + lane];
        a1 += zk * W1[k * 64 + lane + 32];
    }
    z1s[w][lane] = fmaxf(a0, 0.f);
    z1s[w][lane + 32] = fmaxf(a1, 0.f);
    __syncwarp();

    float a = b2[lane];
#pragma unroll
    for (int k = 0; k < 64; k++) a += z1s[w][k] * W2[k * 32 + lane];
    float z2 = fmaxf(a, 0.f);

    float p = z2 * W3[lane];
#pragma unroll
    for (int off = 16; off; off >>= 1) p += __shfl_down_sync(0xffffffffu, p, off);
    if (lane == 0) out[row] = p + b3[0];
}

// ---------------- launch ----------------
extern "C" void kernel_launch(void* const* d_in, const int* in_sizes, int n_in,
                              void* d_out, int out_size) {
    const float* x     = (const float*)d_in[0];
    const void* edge   = d_in[1];
    const void* idxb   = d_in[2];
    const float* x_tab = (const float*)d_in[3];
    const float* Wl1 = (const float*)d_in[4];
    const float* bl1 = (const float*)d_in[5];
    const float* Wr1 = (const float*)d_in[6];
    const float* Wl2 = (const float*)d_in[7];
    const float* bl2 = (const float*)d_in[8];
    const float* Wr2 = (const float*)d_in[9];
    const float* W1  = (const float*)d_in[10];
    const float* b1  = (const float*)d_in[11];
    const float* W2  = (const float*)d_in[12];
    const float* b2  = (const float*)d_in[13];
    const float* W3  = (const float*)d_in[14];
    const float* b3  = (const float*)d_in[15];
    float* out = (float*)d_out;

    int E = in_sizes[1] / 2;
    if (E > E_MAX) E = E_MAX;
    int B = in_sizes[2];
    if (B > B_MAX) B = B_MAX;

    __nv_bfloat16 *p_xh, *p_xl, *p_a1h, *p_a1l, *p_h1ch, *p_h1cl, *p_a2h, *p_a2l;
    __nv_bfloat16 *p_wl1h, *p_wl1l, *p_wr1h, *p_wr1l, *p_wl2h, *p_wl2l, *p_wr2h, *p_wr2l;
    float *p_h1, *p_h2c;
    cudaGetSymbolAddress((void**)&p_xh, g_xh);
    cudaGetSymbolAddress((void**)&p_xl, g_xl);
    cudaGetSymbolAddress((void**)&p_a1h, g_a1h);
    cudaGetSymbolAddress((void**)&p_a1l, g_a1l);
    cudaGetSymbolAddress((void**)&p_h1, g_h1);
    cudaGetSymbolAddress((void**)&p_h1ch, g_h1ch);
    cudaGetSymbolAddress((void**)&p_h1cl, g_h1cl);
    cudaGetSymbolAddress((void**)&p_a2h, g_a2h);
    cudaGetSymbolAddress((void**)&p_a2l, g_a2l);
    cudaGetSymbolAddress((void**)&p_h2c, g_h2c);
    cudaGetSymbolAddress((void**)&p_wl1h, g_wl1h);
    cudaGetSymbolAddress((void**)&p_wl1l, g_wl1l);
    cudaGetSymbolAddress((void**)&p_wr1h, g_wr1h);
    cudaGetSymbolAddress((void**)&p_wr1l, g_wr1l);
    cudaGetSymbolAddress((void**)&p_wl2h, g_wl2h);
    cudaGetSymbolAddress((void**)&p_wl2l, g_wl2l);
    cudaGetSymbolAddress((void**)&p_wr2h, g_wr2h);
    cudaGetSymbolAddress((void**)&p_wr2l, g_wr2l);

    // one-time host objects (created on the un-captured correctness call)
    static cudaStream_t s1 = nullptr, s2 = nullptr;
    static cudaEvent_t ev_root = nullptr, ev_split = nullptr, ev_sel = nullptr,
                       ev_g1 = nullptr, ev_h1c = nullptr;
    if (!s1) {
        cudaStreamCreateWithFlags(&s1, cudaStreamNonBlocking);
        cudaStreamCreateWithFlags(&s2, cudaStreamNonBlocking);
        cudaEventCreateWithFlags(&ev_root, cudaEventDisableTiming);
        cudaEventCreateWithFlags(&ev_split, cudaEventDisableTiming);
        cudaEventCreateWithFlags(&ev_sel, cudaEventDisableTiming);
        cudaEventCreateWithFlags(&ev_g1, cudaEventDisableTiming);
        cudaEventCreateWithFlags(&ev_h1c, cudaEventDisableTiming);
        cudaFuncSetAttribute(gemm_dual_pre_kernel,
                             cudaFuncAttributeMaxDynamicSharedMemorySize, GEMM_SMEM);
    }

    // 0. sniff, then fork
    sniff_kernel<<<1, 32>>>((const int*)edge);
    cudaEventRecord(ev_root, 0);
    cudaStreamWaitEvent(s1, ev_root, 0);
    cudaStreamWaitEvent(s2, ev_root, 0);

    // branch A (default stream): CSR build
    zero_deg_mark_kernel<<<NBLK_SCAN, 256>>>();
    degree_kernel<<<(E + 255) / 256, 256>>>(edge, E);
    blocksum_kernel<<<NBLK_SCAN, 256>>>();
    scan_bsum_kernel<<<1, 512>>>(E);
    distribute_kernel<<<NBLK_SCAN, 256>>>();
    fill_kernel<<<(E + 255) / 256, 256>>>(edge, E);

    // branch B (s1): splits of x and weights
    {
        size_t n4 = (size_t)N_NODES * F_IN / 4;
        split_x_kernel<<<(int)((n4 + 255) / 256), 256, 0, s1>>>(x);
        split_w_kernel<<<(F_IN * 256 + 255) / 256, 256, 0, s1>>>(Wl1, p_wl1h, p_wl1l, F_IN);
        split_w_kernel<<<(F_IN * 256 + 255) / 256, 256, 0, s1>>>(Wr1, p_wr1h, p_wr1l, F_IN);
        split_w_kernel<<<(HID * 256 + 255) / 256, 256, 0, s1>>>(Wl2, p_wl2h, p_wl2l, HID);
        split_w_kernel<<<(HID * 256 + 255) / 256, 256, 0, s1>>>(Wr2, p_wr2h, p_wr2l, HID);
        cudaEventRecord(ev_split, s1);
    }

    // branch C (s2): batch-node selection
    mark_kernel<<<(B + 255) / 256, 256, 0, s2>>>(idxb, B);
    compact_kernel<<<NBLK_SCAN, 256, 0, s2>>>();
    cudaEventRecord(ev_sel, s2);

    // default: layer-1 aggregate (needs CSR only)
    agg1_kernel<<<(N_NODES * 32 + 255) / 256, 256>>>(x);

    // join splits, then gemm1
    cudaStreamWaitEvent(0, ev_split, 0);
    {
        dim3 grid((N_NODES + 127) / 128, 2);
        gemm_dual_pre_kernel<<<grid, 256, GEMM_SMEM>>>(
            p_a1h, p_a1l, F_IN, p_xh, p_xl, F_IN,
            p_wl1h, p_wl1l, p_wr1h, p_wr1l,
            bl1, p_h1, N_NODES);
    }

    // join selection; fork agg2c (default) and split_h1c (s1)
    cudaStreamWaitEvent(0, ev_sel, 0);
    cudaEventRecord(ev_g1, 0);
    cudaStreamWaitEvent(s1, ev_g1, 0);
    split_h1c_kernel<<<(B * 64 + 255) / 256, 256, 0, s1>>>();
    cudaEventRecord(ev_h1c, s1);
    agg2c_kernel<<<(B * 32 + 255) / 256, 256>>>();
    cudaStreamWaitEvent(0, ev_h1c, 0);

    // gemm2 (selected slots)
    {
        dim3 grid((B + 127) / 128, 2);
        gemm_dual_pre_kernel<<<grid, 256, GEMM_SMEM>>>(
            p_a2h, p_a2l, HID, p_h1ch, p_h1cl, HID,
            p_wl2h, p_wl2l, p_wr2h, p_wr2l,
            bl2, p_h2c, B);
    }

    // MLP head
    mlp_kernel<<<(B + 7) / 8, 256>>>(x_tab, idxb, W1, b1, W2, b2, W3, b3, out, B);
}

// round 9
// speedup vs baseline: 6.4936x; 1.0679x over previous
#include <cuda_runtime.h>
#include <cuda_bf16.h>
#include <cstdint>
#include <cstddef>

#define N_NODES 100000
#define F_IN 128
#define HID 256
#define E_MAX 1600000
#define B_MAX 16384
#define NBLK_SCAN ((N_NODES + 255) / 256)

// ---------------- scratch (device globals; no allocation allowed) ----------------
__device__ int g_idx64;
__device__ int g_deg[N_NODES];
__device__ int g_bsum[NBLK_SCAN + 1];
__device__ int g_rowstart[N_NODES + 1];
__device__ int g_wptr[N_NODES];
__device__ int g_csr[E_MAX];

__device__ int g_mark[N_NODES];
__device__ int g_node2slot[N_NODES];
__device__ int g_sel[B_MAX];
__device__ int g_nsel;

__device__ __nv_bfloat16 g_xh[(size_t)N_NODES * F_IN];
__device__ __nv_bfloat16 g_xl[(size_t)N_NODES * F_IN];
__device__ __nv_bfloat16 g_a1h[(size_t)N_NODES * F_IN];
__device__ __nv_bfloat16 g_a1l[(size_t)N_NODES * F_IN];
__device__ float         g_h1[(size_t)N_NODES * HID];
__device__ __nv_bfloat16 g_h1ch[(size_t)B_MAX * HID];
__device__ __nv_bfloat16 g_h1cl[(size_t)B_MAX * HID];
__device__ __nv_bfloat16 g_a2h[(size_t)B_MAX * HID];
__device__ __nv_bfloat16 g_a2l[(size_t)B_MAX * HID];
__device__ float         g_h2c[(size_t)B_MAX * HID];

__device__ __nv_bfloat16 g_wl1h[256 * F_IN], g_wl1l[256 * F_IN];
__device__ __nv_bfloat16 g_wr1h[256 * F_IN], g_wr1l[256 * F_IN];
__device__ __nv_bfloat16 g_wl2h[256 * HID], g_wl2l[256 * HID];
__device__ __nv_bfloat16 g_wr2h[256 * HID], g_wr2l[256 * HID];

// ---------------- helpers ----------------
__device__ __forceinline__ void split1(float v, __nv_bfloat16& h, __nv_bfloat16& l) {
    h = __float2bfloat16(v);
    l = __float2bfloat16(v - __bfloat162float(h));
}

__device__ __forceinline__ void split_store4(float4 v, __nv_bfloat16* ph, __nv_bfloat16* pl) {
    __nv_bfloat16 h0, h1, h2, h3, l0, l1, l2, l3;
    split1(v.x, h0, l0); split1(v.y, h1, l1);
    split1(v.z, h2, l2); split1(v.w, h3, l3);
    __nv_bfloat162* H = reinterpret_cast<__nv_bfloat162*>(ph);
    __nv_bfloat162* L = reinterpret_cast<__nv_bfloat162*>(pl);
    H[0] = __halves2bfloat162(h0, h1);
    H[1] = __halves2bfloat162(h2, h3);
    L[0] = __halves2bfloat162(l0, l1);
    L[1] = __halves2bfloat162(l2, l3);
}

__device__ __forceinline__ uint32_t smem_to_u32(const void* smem_ptr) {
    uint32_t addr;
    asm("{ .reg .u64 tmp; cvta.to.shared.u64 tmp, %1; cvt.u32.u64 %0, tmp; }"
        : "=r"(addr) : "l"(smem_ptr));
    return addr;
}

__device__ __forceinline__ void ldsm_x4(uint32_t* r, uint32_t a) {
    asm volatile("ldmatrix.sync.aligned.m8n8.x4.shared.b16 {%0,%1,%2,%3}, [%4];"
                 : "=r"(r[0]), "=r"(r[1]), "=r"(r[2]), "=r"(r[3]) : "r"(a));
}

__device__ __forceinline__ void cp_async16(uint32_t dst, const void* src, int srcsize) {
    asm volatile("cp.async.ca.shared.global [%0], [%1], 16, %2;"
                 :: "r"(dst), "l"(src), "r"(srcsize));
}
#define CP_COMMIT() asm volatile("cp.async.commit_group;" ::: "memory")
#define CP_WAIT1() asm volatile("cp.async.wait_group 1;" ::: "memory")
#define CP_WAIT0() asm volatile("cp.async.wait_group 0;" ::: "memory")

// ---------------- index dtype sniff ----------------
__global__ void sniff_kernel(const int* __restrict__ e) {
    if (threadIdx.x == 0 && blockIdx.x == 0) {
        int allz = 1;
        for (int i = 0; i < 64; i++)
            if (e[2 * i + 1] != 0) { allz = 0; break; }
        g_idx64 = allz;
    }
}

__device__ __forceinline__ int load_idx(const void* __restrict__ p, size_t i, int is64) {
    if (is64) return (int)((const long long*)p)[i];
    return ((const int*)p)[i];
}

// ---------------- CSR build ----------------
__global__ void zero_deg_mark_kernel() {
    int i = blockIdx.x * blockDim.x + threadIdx.x;
    if (i < N_NODES) {
        g_deg[i] = 0;
        g_mark[i] = 0;
    }
    if (i == 0) g_nsel = 0;
}

__global__ void degree_kernel(const void* __restrict__ edge, int E) {
    int e = blockIdx.x * blockDim.x + threadIdx.x;
    if (e >= E) return;
    int d = load_idx(edge, (size_t)E + e, g_idx64);
    atomicAdd(&g_deg[d], 1);
}

__global__ void blocksum_kernel() {
    __shared__ int ws[8];
    int i = blockIdx.x * 256 + threadIdx.x;
    int v = (i < N_NODES) ? g_deg[i] : 0;
    int lane = threadIdx.x & 31, wid = threadIdx.x >> 5;
#pragma unroll
    for (int o = 16; o; o >>= 1) v += __shfl_down_sync(0xffffffffu, v, o);
    if (lane == 0) ws[wid] = v;
    __syncthreads();
    if (threadIdx.x == 0) {
        int s = 0;
#pragma unroll
        for (int k = 0; k < 8; k++) s += ws[k];
        g_bsum[blockIdx.x] = s;
    }
}

__global__ __launch_bounds__(512) void scan_bsum_kernel(int E) {
    __shared__ int wsum[16];
    int tid = threadIdx.x, lane = tid & 31, wid = tid >> 5;
    int v = (tid < NBLK_SCAN) ? g_bsum[tid] : 0;
    int s = v;
#pragma unroll
    for (int o = 1; o < 32; o <<= 1) {
        int t = __shfl_up_sync(0xffffffffu, s, o);
        if (lane >= o) s += t;
    }
    if (lane == 31) wsum[wid] = s;
    __syncthreads();
    if (wid == 0 && lane < 16) {
        int ws = wsum[lane];
        int ss = ws;
#pragma unroll
        for (int o = 1; o < 16; o <<= 1) {
            int t = __shfl_up_sync(0xffffu, ss, o);
            if (lane >= o) ss += t;
        }
        wsum[lane] = ss;
    }
    __syncthreads();
    int excl = s - v + (wid ? wsum[wid - 1] : 0);
    if (tid < NBLK_SCAN) g_bsum[tid] = excl;
    if (tid == 0) g_rowstart[N_NODES] = E;
}

__global__ void distribute_kernel() {
    __shared__ int wsum[8];
    int tid = threadIdx.x, lane = tid & 31, wid = tid >> 5;
    int i = blockIdx.x * 256 + tid;
    int v = (i < N_NODES) ? g_deg[i] : 0;
    int s = v;
#pragma unroll
    for (int o = 1; o < 32; o <<= 1) {
        int t = __shfl_up_sync(0xffffffffu, s, o);
        if (lane >= o) s += t;
    }
    if (lane == 31) wsum[wid] = s;
    __syncthreads();
    if (wid == 0 && lane < 8) {
        int ws = wsum[lane];
        int ss = ws;
#pragma unroll
        for (int o = 1; o < 8; o <<= 1) {
            int t = __shfl_up_sync(0xffu, ss, o);
            if (lane >= o) ss += t;
        }
        wsum[lane] = ss;
    }
    __syncthreads();
    int excl = s - v + (wid ? wsum[wid - 1] : 0) + g_bsum[blockIdx.x];
    if (i < N_NODES) {
        g_rowstart[i] = excl;
        g_wptr[i] = excl;
    }
}

__global__ void fill_kernel(const void* __restrict__ edge, int E) {
    int e = blockIdx.x * blockDim.x + threadIdx.x;
    if (e >= E) return;
    int is64 = g_idx64;
    int s = load_idx(edge, e, is64);
    int d = load_idx(edge, (size_t)E + e, is64);
    int pos = atomicAdd(&g_wptr[d], 1);
    g_csr[pos] = s;
}

// ---------------- batch node selection ----------------
__global__ void mark_kernel(const void* __restrict__ idx, int B) {
    int r = blockIdx.x * blockDim.x + threadIdx.x;
    if (r >= B) return;
    int node = load_idx(idx, r, g_idx64);
    g_mark[node] = 1;
}

__global__ void compact_kernel() {
    int i = blockIdx.x * blockDim.x + threadIdx.x;
    if (i >= N_NODES) return;
    if (g_mark[i]) {
        int slot = atomicAdd(&g_nsel, 1);
        g_sel[slot] = i;
        g_node2slot[i] = slot;
    }
}

// ---------------- splits ----------------
__global__ void split_x_kernel(const float* __restrict__ x) {
    size_t i = (size_t)blockIdx.x * blockDim.x + threadIdx.x;
    const size_t n4 = (size_t)N_NODES * F_IN / 4;
    if (i >= n4) return;
    float4 v = reinterpret_cast<const float4*>(x)[i];
    split_store4(v, g_xh + i * 4, g_xl + i * 4);
}

__global__ void split_w_kernel(const float* __restrict__ W,
                               __nv_bfloat16* __restrict__ Th,
                               __nv_bfloat16* __restrict__ Tl, int K) {
    int idx = blockIdx.x * blockDim.x + threadIdx.x;
    if (idx >= K * 256) return;
    int k = idx >> 8;
    int n = idx & 255;
    __nv_bfloat16 h, l;
    split1(W[idx], h, l);
    Th[n * K + k] = h;
    Tl[n * K + k] = l;
}

// ---------------- layer-1 aggregate -> bf16 hi/lo ----------------
__global__ __launch_bounds__(256) void agg1_kernel(const float* __restrict__ x) {
    int n = (int)(((size_t)blockIdx.x * blockDim.x + threadIdx.x) >> 5);
    if (n >= N_NODES) return;
    int lane = threadIdx.x & 31;
    int start = g_rowstart[n];
    int end = g_rowstart[n + 1];
    float4 acc0 = make_float4(0.f, 0.f, 0.f, 0.f);
    float4 acc1 = make_float4(0.f, 0.f, 0.f, 0.f);
    int e = start;
    for (; e + 1 < end; e += 2) {
        int s0 = g_csr[e];
        int s1 = g_csr[e + 1];
        float4 v0 = reinterpret_cast<const float4*>(x + (size_t)s0 * F_IN)[lane];
        float4 v1 = reinterpret_cast<const float4*>(x + (size_t)s1 * F_IN)[lane];
        acc0.x += v0.x; acc0.y += v0.y; acc0.z += v0.z; acc0.w += v0.w;
        acc1.x += v1.x; acc1.y += v1.y; acc1.z += v1.z; acc1.w += v1.w;
    }
    if (e < end) {
        int s0 = g_csr[e];
        float4 v0 = reinterpret_cast<const float4*>(x + (size_t)s0 * F_IN)[lane];
        acc0.x += v0.x; acc0.y += v0.y; acc0.z += v0.z; acc0.w += v0.w;
    }
    float r = 1.0f / fmaxf((float)(end - start), 1.0f);
    float4 o;
    o.x = (acc0.x + acc1.x) * r;
    o.y = (acc0.y + acc1.y) * r;
    o.z = (acc0.z + acc1.z) * r;
    o.w = (acc0.w + acc1.w) * r;
    size_t off = (size_t)n * F_IN + lane * 4;
    split_store4(o, g_a1h + off, g_a1l + off);
}

// ---------------- layer-2 aggregate (selected slots) -> bf16 hi/lo ----------------
__global__ __launch_bounds__(256) void agg2c_kernel() {
    int slot = (int)(((size_t)blockIdx.x * blockDim.x + threadIdx.x) >> 5);
    if (slot >= g_nsel) return;
    int n = g_sel[slot];
    int lane = threadIdx.x & 31;
    int start = g_rowstart[n];
    int end = g_rowstart[n + 1];
    float4 a0 = make_float4(0.f, 0.f, 0.f, 0.f);
    float4 a1 = make_float4(0.f, 0.f, 0.f, 0.f);
    for (int e = start; e < end; e++) {
        int s = g_csr[e];
        const float4* hp = reinterpret_cast<const float4*>(g_h1 + (size_t)s * HID);
        float4 v0 = hp[lane];
        float4 v1 = hp[lane + 32];
        a0.x += v0.x; a0.y += v0.y; a0.z += v0.z; a0.w += v0.w;
        a1.x += v1.x; a1.y += v1.y; a1.z += v1.z; a1.w += v1.w;
    }
    float r = 1.0f / fmaxf((float)(end - start), 1.0f);
    a0.x *= r; a0.y *= r; a0.z *= r; a0.w *= r;
    a1.x *= r; a1.y *= r; a1.z *= r; a1.w *= r;
    size_t off = (size_t)slot * HID;
    split_store4(a0, g_a2h + off + lane * 4, g_a2l + off + lane * 4);
    split_store4(a1, g_a2h + off + 128 + lane * 4, g_a2l + off + 128 + lane * 4);
}

// ---------------- bf16x2 tensor-core dual GEMM: cp.async double-buffer + ldmatrix ----------------
__device__ __forceinline__ void mma_bf16(float* c, const uint32_t* a, const uint32_t* b) {
    asm volatile(
        "mma.sync.aligned.m16n8k16.row.col.f32.bf16.bf16.f32 "
        "{%0,%1,%2,%3}, {%4,%5,%6,%7}, {%8,%9}, {%0,%1,%2,%3};"
        : "+f"(c[0]), "+f"(c[1]), "+f"(c[2]), "+f"(c[3])
        : "r"(a[0]), "r"(a[1]), "r"(a[2]), "r"(a[3]), "r"(b[0]), "r"(b[1]));
}

// per buffer: Ah(10240) Al(10240) Bh(10240) Bl(10240); 2 buffers
#define GROWB 80
#define GAB 10240
#define GBUFB 40960
#define GEMM_SMEM 81920

__global__ __launch_bounds__(256, 2) void gemm_dual_pre_kernel(
    const __nv_bfloat16* __restrict__ A0h, const __nv_bfloat16* __restrict__ A0l, int K0,
    const __nv_bfloat16* __restrict__ A1h, const __nv_bfloat16* __restrict__ A1l, int K1,
    const __nv_bfloat16* __restrict__ B0h, const __nv_bfloat16* __restrict__ B0l,
    const __nv_bfloat16* __restrict__ B1h, const __nv_bfloat16* __restrict__ B1l,
    const float* __restrict__ bias, float* __restrict__ C,
    __nv_bfloat16* __restrict__ Ch, __nv_bfloat16* __restrict__ Cl, int M) {
    const int N = 256;
    extern __shared__ char gsm[];
    uint32_t sbase = smem_to_u32(gsm);

    int tid = threadIdx.x;
    int lane = tid & 31;
    int wid = tid >> 5;
    int bm = blockIdx.x * 128;
    int bn = blockIdx.y * 128;
    int wm = (wid >> 2) * 64;
    int wn = (wid & 3) * 32;

    float acc[4][4][4];
#pragma unroll
    for (int mi = 0; mi < 4; mi++)
#pragma unroll
        for (int ni = 0; ni < 4; ni++)
#pragma unroll
            for (int q = 0; q < 4; q++) acc[mi][ni][q] = 0.f;

    int arow = tid >> 1;
    int ak0 = (tid & 1) * 16;
    int g = lane >> 2;
    int tq = (lane & 3) * 2;

    // ldmatrix lane addressing
    int lrA = lane & 15;
    int lcA = (lane >> 4) << 3;
    int lrBoff = ((lane >> 4) << 3) + (lane & 7);    // 0..15 row-within-16 group
    int lcB = ((lane >> 3) & 1) << 3;

    int K = K0 + K1;
    int T = K >> 5;

    int asz = (bm + arow < M) ? 16 : 0;
    uint32_t sA = sbase + arow * GROWB + ak0 * 2;
    uint32_t sB = sbase + 2 * GAB + arow * GROWB + ak0 * 2;

    auto issue = [&](int t, int buf) {
        const __nv_bfloat16 *pah, *pal, *pbh, *pbl;
        int lda, kloc;
        int kt = t << 5;
        if (kt < K0) { pah = A0h; pal = A0l; pbh = B0h; pbl = B0l; lda = K0; kloc = kt; }
        else         { pah = A1h; pal = A1l; pbh = B1h; pbl = B1l; lda = K1; kloc = kt - K0; }
        size_t aoff = (size_t)(bm + arow) * lda + kloc + ak0;
        size_t boff = (size_t)(bn + arow) * lda + kloc + ak0;
        uint32_t bofs = buf * GBUFB;
        cp_async16(sA + bofs, pah + aoff, asz);
        cp_async16(sA + bofs + 16, pah + aoff + 8, asz);
        cp_async16(sA + bofs + GAB, pal + aoff, asz);
        cp_async16(sA + bofs + GAB + 16, pal + aoff + 8, asz);
        cp_async16(sB + bofs, pbh + boff, 16);
        cp_async16(sB + bofs + 16, pbh + boff + 8, 16);
        cp_async16(sB + bofs + GAB, pbl + boff, 16);
        cp_async16(sB + bofs + GAB + 16, pbl + boff + 8, 16);
    };

    issue(0, 0); CP_COMMIT();
    if (T > 1) { issue(1, 1); CP_COMMIT(); }

    for (int t = 0; t < T; t++) {
        if (t == T - 1) { CP_WAIT0(); } else { CP_WAIT1(); }
        __syncthreads();

        int buf = t & 1;
        uint32_t bb = sbase + buf * GBUFB;
#pragma unroll
        for (int ks = 0; ks < 2; ks++) {
            int k0 = ks * 16;
            uint32_t bfh[4][2], bfl[4][2];
            // B: ldmatrix x4 over n-pairs
#pragma unroll
            for (int np = 0; np < 4; np += 2) {
                uint32_t aB = bb + 2 * GAB + (wn + np * 8 + lrBoff) * GROWB + (k0 + lcB) * 2;
                uint32_t r[4];
                ldsm_x4(r, aB);
                bfh[np][0] = r[0]; bfh[np][1] = r[1];
                bfh[np + 1][0] = r[2]; bfh[np + 1][1] = r[3];
                ldsm_x4(r, aB + GAB);
                bfl[np][0] = r[0]; bfl[np][1] = r[1];
                bfl[np + 1][0] = r[2]; bfl[np + 1][1] = r[3];
            }
            uint32_t aA = bb + (wm + lrA) * GROWB + (k0 + lcA) * 2;
#pragma unroll
            for (int mi = 0; mi < 4; mi++) {
                uint32_t ah[4], al[4];
                ldsm_x4(ah, aA + mi * (16 * GROWB));
                ldsm_x4(al, aA + GAB + mi * (16 * GROWB));
#pragma unroll
                for (int ni = 0; ni < 4; ni++) {
                    mma_bf16(acc[mi][ni], ah, bfh[ni]);
                    mma_bf16(acc[mi][ni], ah, bfl[ni]);
                    mma_bf16(acc[mi][ni], al, bfh[ni]);
                }
            }
        }
        __syncthreads();
        if (t + 2 < T) { issue(t + 2, buf); CP_COMMIT(); }
    }

    // epilogue: bias + relu; optional fused compacted bf16 split for marked rows
#pragma unroll
    for (int mi = 0; mi < 4; mi++) {
#pragma unroll
        for (int ni = 0; ni < 4; ni++) {
            int col = bn + wn + ni * 8 + tq;
            float bv0 = bias[col];
            float bv1 = bias[col + 1];
#pragma unroll
            for (int h = 0; h < 2; h++) {
                int r = bm + wm + mi * 16 + g + h * 8;
                if (r < M) {
                    float v0 = fmaxf(acc[mi][ni][h * 2 + 0] + bv0, 0.f);
                    float v1 = fmaxf(acc[mi][ni][h * 2 + 1] + bv1, 0.f);
                    *reinterpret_cast<float2*>(&C[(size_t)r * N + col]) = make_float2(v0, v1);
                    if (Ch && g_mark[r]) {
                        int slot = g_node2slot[r];
                        __nv_bfloat16 h0, h1, l0, l1;
                        split1(v0, h0, l0);
                        split1(v1, h1, l1);
                        *reinterpret_cast<__nv_bfloat162*>(&Ch[(size_t)slot * N + col]) =
                            __halves2bfloat162(h0, h1);
                        *reinterpret_cast<__nv_bfloat162*>(&Cl[(size_t)slot * N + col]) =
                            __halves2bfloat162(l0, l1);
                    }
                }
            }
        }
    }
}

// ---------------- MLP head ----------------
__global__ __launch_bounds__(256) void mlp_kernel(
    const float* __restrict__ x_tab, const void* __restrict__ idx,
    const float* __restrict__ W1, const float* __restrict__ b1,
    const float* __restrict__ W2, const float* __restrict__ b2,
    const float* __restrict__ W3, const float* __restrict__ b3,
    float* __restrict__ out, int B) {
    __shared__ float zs[8][280];
    __shared__ float z1s[8][64];
    int w = threadIdx.x >> 5;
    int lane = threadIdx.x & 31;
    int row = blockIdx.x * 8 + w;
    if (row >= B) return;
    int node = load_idx(idx, row, g_idx64);
    int slot = g_node2slot[node];
    const float4* h = reinterpret_cast<const float4*>(g_h2c + (size_t)slot * HID);
    float4 v = h[lane];
    *reinterpret_cast<float4*>(&zs[w][lane * 4]) = v;
    v = h[lane + 32];
    *reinterpret_cast<float4*>(&zs[w][128 + lane * 4]) = v;
    if (lane < 16) zs[w][256 + lane] = x_tab[row * 16 + lane];
    __syncwarp();

    float a0 = b1[lane];
    float a1 = b1[lane + 32];
#pragma unroll 4
    for (int k = 0; k < 272; k++) {
        float zk = zs[w][k];
        a0 += zk * W1[k * 64 + lane];
        a1 += zk * W1[k * 64 + lane + 32];
    }
    z1s[w][lane] = fmaxf(a0, 0.f);
    z1s[w][lane + 32] = fmaxf(a1, 0.f);
    __syncwarp();

    float a = b2[lane];
#pragma unroll
    for (int k = 0; k < 64; k++) a += z1s[w][k] * W2[k * 32 + lane];
    float z2 = fmaxf(a, 0.f);

    float p = z2 * W3[lane];
#pragma unroll
    for (int off = 16; off; off >>= 1) p += __shfl_down_sync(0xffffffffu, p, off);
    if (lane == 0) out[row] = p + b3[0];
}

// ---------------- launch ----------------
extern "C" void kernel_launch(void* const* d_in, const int* in_sizes, int n_in,
                              void* d_out, int out_size) {
    const float* x     = (const float*)d_in[0];
    const void* edge   = d_in[1];
    const void* idxb   = d_in[2];
    const float* x_tab = (const float*)d_in[3];
    const float* Wl1 = (const float*)d_in[4];
    const float* bl1 = (const float*)d_in[5];
    const float* Wr1 = (const float*)d_in[6];
    const float* Wl2 = (const float*)d_in[7];
    const float* bl2 = (const float*)d_in[8];
    const float* Wr2 = (const float*)d_in[9];
    const float* W1  = (const float*)d_in[10];
    const float* b1  = (const float*)d_in[11];
    const float* W2  = (const float*)d_in[12];
    const float* b2  = (const float*)d_in[13];
    const float* W3  = (const float*)d_in[14];
    const float* b3  = (const float*)d_in[15];
    float* out = (float*)d_out;

    int E = in_sizes[1] / 2;
    if (E > E_MAX) E = E_MAX;
    int B = in_sizes[2];
    if (B > B_MAX) B = B_MAX;

    __nv_bfloat16 *p_xh, *p_xl, *p_a1h, *p_a1l, *p_h1ch, *p_h1cl, *p_a2h, *p_a2l;
    __nv_bfloat16 *p_wl1h, *p_wl1l, *p_wr1h, *p_wr1l, *p_wl2h, *p_wl2l, *p_wr2h, *p_wr2l;
    float *p_h1, *p_h2c;
    cudaGetSymbolAddress((void**)&p_xh, g_xh);
    cudaGetSymbolAddress((void**)&p_xl, g_xl);
    cudaGetSymbolAddress((void**)&p_a1h, g_a1h);
    cudaGetSymbolAddress((void**)&p_a1l, g_a1l);
    cudaGetSymbolAddress((void**)&p_h1, g_h1);
    cudaGetSymbolAddress((void**)&p_h1ch, g_h1ch);
    cudaGetSymbolAddress((void**)&p_h1cl, g_h1cl);
    cudaGetSymbolAddress((void**)&p_a2h, g_a2h);
    cudaGetSymbolAddress((void**)&p_a2l, g_a2l);
    cudaGetSymbolAddress((void**)&p_h2c, g_h2c);
    cudaGetSymbolAddress((void**)&p_wl1h, g_wl1h);
    cudaGetSymbolAddress((void**)&p_wl1l, g_wl1l);
    cudaGetSymbolAddress((void**)&p_wr1h, g_wr1h);
    cudaGetSymbolAddress((void**)&p_wr1l, g_wr1l);
    cudaGetSymbolAddress((void**)&p_wl2h, g_wl2h);
    cudaGetSymbolAddress((void**)&p_wl2l, g_wl2l);
    cudaGetSymbolAddress((void**)&p_wr2h, g_wr2h);
    cudaGetSymbolAddress((void**)&p_wr2l, g_wr2l);

    static cudaStream_t s1 = nullptr, s2 = nullptr;
    static cudaEvent_t ev_root = nullptr, ev_split = nullptr, ev_sel = nullptr;
    if (!s1) {
        cudaStreamCreateWithFlags(&s1, cudaStreamNonBlocking);
        cudaStreamCreateWithFlags(&s2, cudaStreamNonBlocking);
        cudaEventCreateWithFlags(&ev_root, cudaEventDisableTiming);
        cudaEventCreateWithFlags(&ev_split, cudaEventDisableTiming);
        cudaEventCreateWithFlags(&ev_sel, cudaEventDisableTiming);
        cudaFuncSetAttribute(gemm_dual_pre_kernel,
                             cudaFuncAttributeMaxDynamicSharedMemorySize, GEMM_SMEM);
    }

    // 0. sniff, then fork
    sniff_kernel<<<1, 32>>>((const int*)edge);
    cudaEventRecord(ev_root, 0);
    cudaStreamWaitEvent(s1, ev_root, 0);
    cudaStreamWaitEvent(s2, ev_root, 0);

    // branch A (default): CSR build
    zero_deg_mark_kernel<<<NBLK_SCAN, 256>>>();
    degree_kernel<<<(E + 255) / 256, 256>>>(edge, E);
    blocksum_kernel<<<NBLK_SCAN, 256>>>();
    scan_bsum_kernel<<<1, 512>>>(E);
    distribute_kernel<<<NBLK_SCAN, 256>>>();
    fill_kernel<<<(E + 255) / 256, 256>>>(edge, E);

    // branch B (s1): splits
    {
        size_t n4 = (size_t)N_NODES * F_IN / 4;
        split_x_kernel<<<(int)((n4 + 255) / 256), 256, 0, s1>>>(x);
        split_w_kernel<<<(F_IN * 256 + 255) / 256, 256, 0, s1>>>(Wl1, p_wl1h, p_wl1l, F_IN);
        split_w_kernel<<<(F_IN * 256 + 255) / 256, 256, 0, s1>>>(Wr1, p_wr1h, p_wr1l, F_IN);
        split_w_kernel<<<(HID * 256 + 255) / 256, 256, 0, s1>>>(Wl2, p_wl2h, p_wl2l, HID);
        split_w_kernel<<<(HID * 256 + 255) / 256, 256, 0, s1>>>(Wr2, p_wr2h, p_wr2l, HID);
        cudaEventRecord(ev_split, s1);
    }

    // branch C (s2): batch-node selection (note: mark/node2slot read by gemm1 epilogue)
    mark_kernel<<<(B + 255) / 256, 256, 0, s2>>>(idxb, B);
    compact_kernel<<<NBLK_SCAN, 256, 0, s2>>>();
    cudaEventRecord(ev_sel, s2);

    // default: layer-1 aggregate (needs CSR only)
    agg1_kernel<<<(N_NODES * 32 + 255) / 256, 256>>>(x);

    // join splits + selection, then gemm1 (fused compacted h1 split)
    cudaStreamWaitEvent(0, ev_split, 0);
    cudaStreamWaitEvent(0, ev_sel, 0);
    {
        dim3 grid((N_NODES + 127) / 128, 2);
        gemm_dual_pre_kernel<<<grid, 256, GEMM_SMEM>>>(
            p_a1h, p_a1l, F_IN, p_xh, p_xl, F_IN,
            p_wl1h, p_wl1l, p_wr1h, p_wr1l,
            bl1, p_h1, p_h1ch, p_h1cl, N_NODES);
    }

    // layer-2 aggregate (selected slots)
    agg2c_kernel<<<(B * 32 + 255) / 256, 256>>>();

    // gemm2 (selected slots)
    {
        dim3 grid((B + 127) / 128, 2);
        gemm_dual_pre_kernel<<<grid, 256, GEMM_SMEM>>>(
            p_a2h, p_a2l, HID, p_h1ch, p_h1cl, HID,
            p_wl2h, p_wl2l, p_wr2h, p_wr2l,
            bl2, p_h2c, (__nv_bfloat16*)nullptr, (__nv_bfloat16*)nullptr, B);
    }

    // MLP head
    mlp_kernel<<<(B + 7) / 8, 256>>>(x_tab, idxb, W1, b1, W2, b2, W3, b3, out, B);
}